// round 1
// baseline (speedup 1.0000x reference)
#include <cuda_runtime.h>
#include <math.h>
#include <stdint.h>

// Problem constants
#define NTOK 4096            // B*T
#define DIMK 1024
#define NHEAD 16
#define DHEAD 64

// ---------------- scratch (device globals; no allocs allowed) ----------------
__device__ float g_xn[NTOK * DIMK];
__device__ float g_mn[NTOK * DIMK];
__device__ float g_q [NTOK * DIMK];
__device__ float g_k [NTOK * DIMK];
__device__ float g_v [NTOK * DIMK];
__device__ float g_att[NTOK * DIMK];
__device__ float g_lowq[NTOK * 8];
__device__ float g_lowk[NTOK * 8];
__device__ float g_lowv[NTOK * 8];
__device__ float g_go  [NTOK * 8];
__device__ float g_lowo[NTOK * 8];

// ---------------- LayerNorm: one block (256 thr) per row of 1024 ----------------
__global__ void ln_kernel(const float* __restrict__ in, const float* __restrict__ g,
                          const float* __restrict__ b, float* __restrict__ out)
{
    int row = blockIdx.x;
    int tid = threadIdx.x;
    float4 a = ((const float4*)(in + (size_t)row * DIMK))[tid];
    float s = a.x + a.y + a.z + a.w;
    float q = a.x*a.x + a.y*a.y + a.z*a.z + a.w*a.w;
    #pragma unroll
    for (int o = 16; o; o >>= 1) {
        s += __shfl_xor_sync(0xffffffffu, s, o);
        q += __shfl_xor_sync(0xffffffffu, q, o);
    }
    __shared__ float ss[8], sq[8];
    __shared__ float s_mean, s_rstd;
    int warp = tid >> 5, lane = tid & 31;
    if (lane == 0) { ss[warp] = s; sq[warp] = q; }
    __syncthreads();
    if (tid == 0) {
        float ts = 0.f, tq = 0.f;
        #pragma unroll
        for (int i = 0; i < 8; i++) { ts += ss[i]; tq += sq[i]; }
        float mean = ts * (1.0f / DIMK);
        float var  = tq * (1.0f / DIMK) - mean * mean;
        s_mean = mean;
        s_rstd = rsqrtf(var + 1e-5f);
    }
    __syncthreads();
    float mean = s_mean, rstd = s_rstd;
    float4 gg = ((const float4*)g)[tid];
    float4 bb = ((const float4*)b)[tid];
    float4 r;
    r.x = (a.x - mean) * rstd * gg.x + bb.x;
    r.y = (a.y - mean) * rstd * gg.y + bb.y;
    r.z = (a.z - mean) * rstd * gg.z + bb.z;
    r.w = (a.w - mean) * rstd * gg.w + bb.w;
    ((float4*)(out + (size_t)row * DIMK))[tid] = r;
}

// ---------------- rank-8 projections + gates for q/k/v (one block per token) ----------------
__global__ void lowrank_qkv_kernel(
    const float* __restrict__ Aq, const float* __restrict__ Ak, const float* __restrict__ Av,
    const float* __restrict__ Gq, const float* __restrict__ Gk, const float* __restrict__ Gv,
    const float* __restrict__ Go)
{
    int t = blockIdx.x;
    int tid = threadIdx.x;          // 128
    int warp = tid >> 5, lane = tid & 31;
    const float4* xr = (const float4*)(g_xn + (size_t)t * DIMK);
    const float4* mr = (const float4*)(g_mn + (size_t)t * DIMK);
    __shared__ float res[56];
    for (int d = warp; d < 56; d += 4) {
        const float4* vec;
        const float4* src;
        if (d < 8)       { vec = (const float4*)(Aq + d * DIMK);        src = xr; }
        else if (d < 16) { vec = (const float4*)(Ak + (d - 8) * DIMK);  src = xr; }
        else if (d < 24) { vec = (const float4*)(Av + (d - 16) * DIMK); src = xr; }
        else if (d < 32) { vec = (const float4*)(Gq + (d - 24) * DIMK); src = mr; }
        else if (d < 40) { vec = (const float4*)(Gk + (d - 32) * DIMK); src = mr; }
        else if (d < 48) { vec = (const float4*)(Gv + (d - 40) * DIMK); src = mr; }
        else             { vec = (const float4*)(Go + (d - 48) * DIMK); src = mr; }
        float sacc = 0.f;
        for (int i = lane; i < DIMK / 4; i += 32) {
            float4 u = src[i], w = vec[i];
            sacc += u.x*w.x + u.y*w.y + u.z*w.z + u.w*w.w;
        }
        #pragma unroll
        for (int o = 16; o; o >>= 1) sacc += __shfl_xor_sync(0xffffffffu, sacc, o);
        if (lane == 0) res[d] = sacc;
    }
    __syncthreads();
    if (tid < 8) {
        g_lowq[t*8 + tid] = 0.25f * res[tid]      * res[24 + tid];
        g_lowk[t*8 + tid] = 0.25f * res[8 + tid]  * res[32 + tid];
        g_lowv[t*8 + tid] = 0.25f * res[16 + tid] * res[40 + tid];
        g_go  [t*8 + tid] = res[48 + tid];
    }
}

// ---------------- rank-8 projection for o (after attention) ----------------
__global__ void lowrank_o_kernel(const float* __restrict__ Ao)
{
    int t = blockIdx.x;
    int tid = threadIdx.x;          // 128
    int warp = tid >> 5, lane = tid & 31;
    __shared__ float res[8];
    const float4* ar = (const float4*)(g_att + (size_t)t * DIMK);
    for (int d = warp; d < 8; d += 4) {
        const float4* vec = (const float4*)(Ao + d * DIMK);
        float sacc = 0.f;
        for (int i = lane; i < DIMK / 4; i += 32) {
            float4 u = ar[i], w = vec[i];
            sacc += u.x*w.x + u.y*w.y + u.z*w.z + u.w*w.w;
        }
        #pragma unroll
        for (int o = 16; o; o >>= 1) sacc += __shfl_xor_sync(0xffffffffu, sacc, o);
        if (lane == 0) res[d] = sacc;
    }
    __syncthreads();
    if (tid < 8) g_lowo[t*8 + tid] = 0.25f * res[tid] * g_go[t*8 + tid];
}

// ---------------- fused GEMM + rank-8 LoRA:  C[M,N] = X[M,K]·W[N,K]^T + low[M,8]·Bm[N,8]^T ----------------
// 128x128 tile, BK=8, 256 threads, 8x8 per thread. LoRA term = one extra BK iteration.
__global__ __launch_bounds__(256, 2)
void gemm_lora_kernel(const float* __restrict__ X, const float* __restrict__ W,
                      const float* __restrict__ low, const float* __restrict__ Bm,
                      float* __restrict__ C)
{
    const int K = DIMK, N = DIMK;
    __shared__ float As[8][132];
    __shared__ float Ws[8][132];
    int bm = blockIdx.y * 128, bn = blockIdx.x * 128;
    int tid = threadIdx.x;
    int tx = tid & 15, ty = tid >> 4;
    int arow = tid >> 1;
    int acol = (tid & 1) << 2;
    const float* Xp = X + (size_t)(bm + arow) * K + acol;
    const float* Wp = W + (size_t)(bn + arow) * K + acol;
    const float* Lp = low + (size_t)(bm + arow) * 8 + acol;
    const float* Bp = Bm  + (size_t)(bn + arow) * 8 + acol;

    float acc[8][8];
    #pragma unroll
    for (int i = 0; i < 8; i++)
        #pragma unroll
        for (int j = 0; j < 8; j++) acc[i][j] = 0.f;

    float4 av = *(const float4*)(Xp);
    float4 wv = *(const float4*)(Wp);

    for (int it = 0; it <= 128; ++it) {
        As[acol+0][arow] = av.x; As[acol+1][arow] = av.y;
        As[acol+2][arow] = av.z; As[acol+3][arow] = av.w;
        Ws[acol+0][arow] = wv.x; Ws[acol+1][arow] = wv.y;
        Ws[acol+2][arow] = wv.z; Ws[acol+3][arow] = wv.w;
        __syncthreads();

        float4 nav, nwv;
        if (it < 127) {                       // prefetch next X/W tile
            nav = *(const float4*)(Xp + (it + 1) * 8);
            nwv = *(const float4*)(Wp + (it + 1) * 8);
        } else if (it == 127) {               // prefetch the LoRA rank-8 "tile"
            nav = *(const float4*)(Lp);
            nwv = *(const float4*)(Bp);
        }

        #pragma unroll
        for (int kk = 0; kk < 8; kk++) {
            float a[8], w[8];
            *(float4*)&a[0] = *(const float4*)&As[kk][ty * 4];
            *(float4*)&a[4] = *(const float4*)&As[kk][64 + ty * 4];
            *(float4*)&w[0] = *(const float4*)&Ws[kk][tx * 4];
            *(float4*)&w[4] = *(const float4*)&Ws[kk][64 + tx * 4];
            #pragma unroll
            for (int i = 0; i < 8; i++)
                #pragma unroll
                for (int j = 0; j < 8; j++)
                    acc[i][j] += a[i] * w[j];
        }
        __syncthreads();
        av = nav; wv = nwv;
    }

    #pragma unroll
    for (int i = 0; i < 8; i++) {
        int r = bm + ty * 4 + (i & 3) + ((i >> 2) << 6);
        float4 o0 = make_float4(acc[i][0], acc[i][1], acc[i][2], acc[i][3]);
        float4 o1 = make_float4(acc[i][4], acc[i][5], acc[i][6], acc[i][7]);
        *(float4*)(C + (size_t)r * N + bn + tx * 4)      = o0;
        *(float4*)(C + (size_t)r * N + bn + 64 + tx * 4) = o1;
    }
}

// ---------------- flash attention, block-causal (frame=256) ----------------
// Tiles: 64 queries x 64 keys, DH=64. Mask never cuts a tile -> no masking in-kernel.
// XOR-swizzled smem (exactly 48KB static), softmax stats in registers (16-lane shuffle groups).
__device__ __forceinline__ int swz(int row, int col4) {
    return (row << 6) + (((col4 ^ (row >> 2)) & 15) << 2);
}

__global__ __launch_bounds__(256)
void attn_kernel(const float* __restrict__ q, const float* __restrict__ k,
                 const float* __restrict__ v, float* __restrict__ o)
{
    __shared__ float Qs[4096];   // Q^T  [dh][tok], swizzled
    __shared__ float KPs[4096];  // K^T then P [tk][q], swizzled
    __shared__ float Vs[4096];   // V natural [tok][dh]

    int qt = 31 - (int)blockIdx.x;           // big frames first (load balance)
    int h  = blockIdx.y;
    int b  = blockIdx.z;
    int t0 = qt << 6;
    int ntile = ((qt >> 2) + 1) << 2;        // allowed key tiles
    int tid = threadIdx.x;
    int tx = tid & 15, ty = tid >> 4;
    size_t base = ((size_t)b * 2048) * DIMK + h * DHEAD;
    const float* qb = q + base;
    const float* kb = k + base;
    const float* vb = v + base;

    // load Q tile transposed+swizzled
    for (int i = tid; i < 1024; i += 256) {
        int tok = i >> 4, c4 = i & 15, dh = c4 << 2;
        float4 val = *(const float4*)(qb + (size_t)(t0 + tok) * DIMK + dh);
        int c = tok >> 2, rmod = tok & 3;
        Qs[swz(dh + 0, c) + rmod] = val.x;
        Qs[swz(dh + 1, c) + rmod] = val.y;
        Qs[swz(dh + 2, c) + rmod] = val.z;
        Qs[swz(dh + 3, c) + rmod] = val.w;
    }

    float acc[4][4];
    #pragma unroll
    for (int i = 0; i < 4; i++)
        #pragma unroll
        for (int j = 0; j < 4; j++) acc[i][j] = 0.f;
    float mreg[4] = {-1e30f, -1e30f, -1e30f, -1e30f};
    float lreg[4] = {0.f, 0.f, 0.f, 0.f};

    for (int kt = 0; kt < ntile; ++kt) {
        __syncthreads();   // Q ready (first iter) / prev-iter KPs,Vs reads done
        const float* kp = kb + (size_t)(kt << 6) * DIMK;
        const float* vp = vb + (size_t)(kt << 6) * DIMK;
        for (int i = tid; i < 1024; i += 256) {
            int tok = i >> 4, c4 = i & 15, dh = c4 << 2;
            float4 kvv = *(const float4*)(kp + (size_t)tok * DIMK + dh);
            int c = tok >> 2, rmod = tok & 3;
            KPs[swz(dh + 0, c) + rmod] = kvv.x;
            KPs[swz(dh + 1, c) + rmod] = kvv.y;
            KPs[swz(dh + 2, c) + rmod] = kvv.z;
            KPs[swz(dh + 3, c) + rmod] = kvv.w;
            float4 vvv = *(const float4*)(vp + (size_t)tok * DIMK + dh);
            *(float4*)&Vs[(tok << 6) + dh] = vvv;
        }
        __syncthreads();

        // S = (Q K^T) * scale
        float s[4][4];
        #pragma unroll
        for (int i = 0; i < 4; i++)
            #pragma unroll
            for (int j = 0; j < 4; j++) s[i][j] = 0.f;
        #pragma unroll 8
        for (int kk = 0; kk < 64; ++kk) {
            float qa[4], ka[4];
            *(float4*)&qa[0] = *(const float4*)&Qs[swz(kk, ty)];
            *(float4*)&ka[0] = *(const float4*)&KPs[swz(kk, tx)];
            #pragma unroll
            for (int i = 0; i < 4; i++)
                #pragma unroll
                for (int j = 0; j < 4; j++)
                    s[i][j] += qa[i] * ka[j];
        }
        __syncthreads();   // all K reads done before P overwrites KPs

        // online softmax (rows owned by 16-lane groups; stats replicated in regs)
        float p[4][4];
        #pragma unroll
        for (int i = 0; i < 4; i++) {
            #pragma unroll
            for (int j = 0; j < 4; j++) s[i][j] *= 0.125f;
            float rm = fmaxf(fmaxf(s[i][0], s[i][1]), fmaxf(s[i][2], s[i][3]));
            #pragma unroll
            for (int off = 8; off; off >>= 1)
                rm = fmaxf(rm, __shfl_xor_sync(0xffffffffu, rm, off));
            float mnew = fmaxf(mreg[i], rm);
            float corr = __expf(mreg[i] - mnew);
            mreg[i] = mnew;
            float ps = 0.f;
            #pragma unroll
            for (int j = 0; j < 4; j++) { p[i][j] = __expf(s[i][j] - mnew); ps += p[i][j]; }
            #pragma unroll
            for (int off = 8; off; off >>= 1)
                ps += __shfl_xor_sync(0xffffffffu, ps, off);
            lreg[i] = lreg[i] * corr + ps;
            #pragma unroll
            for (int j = 0; j < 4; j++) acc[i][j] *= corr;
        }
        // store P as [tk][q] into KPs
        #pragma unroll
        for (int i = 0; i < 4; i++)
            #pragma unroll
            for (int j = 0; j < 4; j++)
                KPs[swz((tx << 2) + j, ty) + i] = p[i][j];
        __syncthreads();

        // O += P V
        #pragma unroll 8
        for (int kk = 0; kk < 64; ++kk) {
            float pa[4], va[4];
            *(float4*)&pa[0] = *(const float4*)&KPs[swz(kk, ty)];
            *(float4*)&va[0] = *(const float4*)&Vs[(kk << 6) + (tx << 2)];
            #pragma unroll
            for (int i = 0; i < 4; i++)
                #pragma unroll
                for (int j = 0; j < 4; j++)
                    acc[i][j] += pa[i] * va[j];
        }
    }

    #pragma unroll
    for (int i = 0; i < 4; i++) {
        float inv = 1.0f / lreg[i];
        float4 r = make_float4(acc[i][0]*inv, acc[i][1]*inv, acc[i][2]*inv, acc[i][3]*inv);
        *(float4*)(o + base + (size_t)(t0 + (ty << 2) + i) * DIMK + (tx << 2)) = r;
    }
}

// ---------------- launch ----------------
extern "C" void kernel_launch(void* const* d_in, const int* in_sizes, int n_in,
                              void* d_out, int out_size)
{
    (void)in_sizes; (void)n_in; (void)out_size;
    const float* x      = (const float*)d_in[0];
    const float* m_tok  = (const float*)d_in[1];
    const float* norm_g = (const float*)d_in[2];
    const float* norm_b = (const float*)d_in[3];
    const float* mnorm_g= (const float*)d_in[4];
    const float* mnorm_b= (const float*)d_in[5];
    const float* Wq = (const float*)d_in[6];
    const float* Aq = (const float*)d_in[7];
    const float* Bq = (const float*)d_in[8];
    const float* Gq = (const float*)d_in[9];
    const float* Wk = (const float*)d_in[10];
    const float* Ak = (const float*)d_in[11];
    const float* Bk = (const float*)d_in[12];
    const float* Gk = (const float*)d_in[13];
    const float* Wv = (const float*)d_in[14];
    const float* Av = (const float*)d_in[15];
    const float* Bv = (const float*)d_in[16];
    const float* Gv = (const float*)d_in[17];
    const float* Wo = (const float*)d_in[18];
    const float* Ao = (const float*)d_in[19];
    const float* Bo = (const float*)d_in[20];
    const float* Go = (const float*)d_in[21];
    float* out = (float*)d_out;

    float *p_xn, *p_mn, *p_q, *p_k, *p_v, *p_att, *p_lowq, *p_lowk, *p_lowv, *p_lowo;
    cudaGetSymbolAddress((void**)&p_xn,  g_xn);
    cudaGetSymbolAddress((void**)&p_mn,  g_mn);
    cudaGetSymbolAddress((void**)&p_q,   g_q);
    cudaGetSymbolAddress((void**)&p_k,   g_k);
    cudaGetSymbolAddress((void**)&p_v,   g_v);
    cudaGetSymbolAddress((void**)&p_att, g_att);
    cudaGetSymbolAddress((void**)&p_lowq, g_lowq);
    cudaGetSymbolAddress((void**)&p_lowk, g_lowk);
    cudaGetSymbolAddress((void**)&p_lowv, g_lowv);
    cudaGetSymbolAddress((void**)&p_lowo, g_lowo);

    ln_kernel<<<NTOK, 256>>>(x,     norm_g,  norm_b,  p_xn);
    ln_kernel<<<NTOK, 256>>>(m_tok, mnorm_g, mnorm_b, p_mn);
    lowrank_qkv_kernel<<<NTOK, 128>>>(Aq, Ak, Av, Gq, Gk, Gv, Go);

    dim3 gg(8, 32);
    gemm_lora_kernel<<<gg, 256>>>(p_xn, Wq, p_lowq, Bq, p_q);
    gemm_lora_kernel<<<gg, 256>>>(p_xn, Wk, p_lowk, Bk, p_k);
    gemm_lora_kernel<<<gg, 256>>>(p_xn, Wv, p_lowv, Bv, p_v);

    attn_kernel<<<dim3(32, 16, 2), 256>>>(p_q, p_k, p_v, p_att);

    lowrank_o_kernel<<<NTOK, 128>>>(Ao);
    gemm_lora_kernel<<<gg, 256>>>(p_att, Wo, p_lowo, Bo, out);
}

// round 3
// speedup vs baseline: 1.2910x; 1.2910x over previous
#include <cuda_runtime.h>
#include <cuda_bf16.h>
#include <math.h>
#include <stdint.h>

#define NTOK 4096            // B*T
#define DIMK 1024
#define NHEAD 16
#define DHEAD 64

// ---------------- scratch (device globals; no allocs allowed) ----------------
__device__ float g_xn [NTOK * DIMK];
__device__ float g_mn [NTOK * DIMK];
__device__ float g_q  [NTOK * DIMK];
__device__ float g_k  [NTOK * DIMK];
__device__ float g_v  [NTOK * DIMK];
__device__ float g_att[NTOK * DIMK];
__device__ float g_go [NTOK * 8];

__device__ __nv_bfloat16 g_xn_h [NTOK * DIMK];
__device__ __nv_bfloat16 g_xn_l [NTOK * DIMK];
__device__ __nv_bfloat16 g_att_h[NTOK * DIMK];
__device__ __nv_bfloat16 g_att_l[NTOK * DIMK];
__device__ __nv_bfloat16 g_w_h  [4 * DIMK * DIMK];
__device__ __nv_bfloat16 g_w_l  [4 * DIMK * DIMK];
__device__ __nv_bfloat16 g_b16_h[4 * DIMK * 16];
__device__ __nv_bfloat16 g_b16_l[4 * DIMK * 16];
__device__ __nv_bfloat16 g_lq_h [NTOK * 16];
__device__ __nv_bfloat16 g_lq_l [NTOK * 16];
__device__ __nv_bfloat16 g_lk_h [NTOK * 16];
__device__ __nv_bfloat16 g_lk_l [NTOK * 16];
__device__ __nv_bfloat16 g_lv_h [NTOK * 16];
__device__ __nv_bfloat16 g_lv_l [NTOK * 16];
__device__ __nv_bfloat16 g_lo_h [NTOK * 16];
__device__ __nv_bfloat16 g_lo_l [NTOK * 16];

// ---------------- helpers ----------------
__device__ __forceinline__ uint32_t smem_u32(const void* p) {
    uint32_t a;
    asm("{ .reg .u64 t; cvta.to.shared.u64 t, %1; cvt.u32.u64 %0, t; }" : "=r"(a) : "l"(p));
    return a;
}

__device__ __forceinline__ void cpa16(uint32_t s, const void* g) {
    asm volatile("cp.async.cg.shared.global [%0], [%1], 16;" :: "r"(s), "l"(g));
}
#define CP_COMMIT() asm volatile("cp.async.commit_group;" ::: "memory")
#define CP_WAIT1()  asm volatile("cp.async.wait_group 1;" ::: "memory")
#define CP_WAIT0()  asm volatile("cp.async.wait_group 0;" ::: "memory")

__device__ __forceinline__ void ldsm4(uint32_t* r, uint32_t addr) {
    asm volatile("ldmatrix.sync.aligned.m8n8.x4.shared.b16 {%0,%1,%2,%3}, [%4];"
        : "=r"(r[0]), "=r"(r[1]), "=r"(r[2]), "=r"(r[3]) : "r"(addr));
}

__device__ __forceinline__ void mma16816(float* c, const uint32_t* a, const uint32_t* b) {
    asm volatile(
        "mma.sync.aligned.m16n8k16.row.col.f32.bf16.bf16.f32 "
        "{%0,%1,%2,%3}, {%4,%5,%6,%7}, {%8,%9}, {%0,%1,%2,%3};"
        : "+f"(c[0]), "+f"(c[1]), "+f"(c[2]), "+f"(c[3])
        : "r"(a[0]), "r"(a[1]), "r"(a[2]), "r"(a[3]), "r"(b[0]), "r"(b[1]));
}

__device__ __forceinline__ uint32_t swz128u(uint32_t o) { return o ^ ((o >> 3) & 0x70); }

__device__ __forceinline__ void splitf(float x, __nv_bfloat16& h, __nv_bfloat16& l) {
    h = __float2bfloat16(x);
    l = __float2bfloat16(x - __bfloat162float(h));
}

// ---------------- LayerNorm + optional hi/lo bf16 output ----------------
__global__ void ln_kernel(const float* __restrict__ in, const float* __restrict__ g,
                          const float* __restrict__ b, float* __restrict__ out,
                          __nv_bfloat16* __restrict__ hi, __nv_bfloat16* __restrict__ lo)
{
    int row = blockIdx.x;
    int tid = threadIdx.x;
    float4 a = ((const float4*)(in + (size_t)row * DIMK))[tid];
    float s = a.x + a.y + a.z + a.w;
    float q = a.x*a.x + a.y*a.y + a.z*a.z + a.w*a.w;
    #pragma unroll
    for (int o = 16; o; o >>= 1) {
        s += __shfl_xor_sync(0xffffffffu, s, o);
        q += __shfl_xor_sync(0xffffffffu, q, o);
    }
    __shared__ float ss[8], sq[8];
    __shared__ float s_mean, s_rstd;
    int warp = tid >> 5, lane = tid & 31;
    if (lane == 0) { ss[warp] = s; sq[warp] = q; }
    __syncthreads();
    if (tid == 0) {
        float ts = 0.f, tq = 0.f;
        #pragma unroll
        for (int i = 0; i < 8; i++) { ts += ss[i]; tq += sq[i]; }
        float mean = ts * (1.0f / DIMK);
        float var  = tq * (1.0f / DIMK) - mean * mean;
        s_mean = mean;
        s_rstd = rsqrtf(var + 1e-5f);
    }
    __syncthreads();
    float mean = s_mean, rstd = s_rstd;
    float4 gg = ((const float4*)g)[tid];
    float4 bb = ((const float4*)b)[tid];
    float4 r;
    r.x = (a.x - mean) * rstd * gg.x + bb.x;
    r.y = (a.y - mean) * rstd * gg.y + bb.y;
    r.z = (a.z - mean) * rstd * gg.z + bb.z;
    r.w = (a.w - mean) * rstd * gg.w + bb.w;
    ((float4*)(out + (size_t)row * DIMK))[tid] = r;
    if (hi) {
        __nv_bfloat16 h0,h1,h2,h3,l0,l1,l2,l3;
        splitf(r.x,h0,l0); splitf(r.y,h1,l1); splitf(r.z,h2,l2); splitf(r.w,h3,l3);
        __nv_bfloat162 hA; hA.x=h0; hA.y=h1;
        __nv_bfloat162 hB; hB.x=h2; hB.y=h3;
        __nv_bfloat162 lA; lA.x=l0; lA.y=l1;
        __nv_bfloat162 lB; lB.x=l2; lB.y=l3;
        ((__nv_bfloat162*)(hi + (size_t)row * DIMK))[tid*2]   = hA;
        ((__nv_bfloat162*)(hi + (size_t)row * DIMK))[tid*2+1] = hB;
        ((__nv_bfloat162*)(lo + (size_t)row * DIMK))[tid*2]   = lA;
        ((__nv_bfloat162*)(lo + (size_t)row * DIMK))[tid*2+1] = lB;
    }
}

// ---------------- fp32 -> hi/lo bf16 weight conversion ----------------
__global__ void cvt_w_kernel(const float* __restrict__ in, int slot)
{
    size_t i = (size_t)blockIdx.x * blockDim.x + threadIdx.x;   // n/4 threads
    float4 v = ((const float4*)in)[i];
    __nv_bfloat16 h0,h1,h2,h3,l0,l1,l2,l3;
    splitf(v.x,h0,l0); splitf(v.y,h1,l1); splitf(v.z,h2,l2); splitf(v.w,h3,l3);
    size_t o = (size_t)slot * DIMK * DIMK + i * 4;
    __nv_bfloat162 hA; hA.x=h0; hA.y=h1;
    __nv_bfloat162 hB; hB.x=h2; hB.y=h3;
    __nv_bfloat162 lA; lA.x=l0; lA.y=l1;
    __nv_bfloat162 lB; lB.x=l2; lB.y=l3;
    *(__nv_bfloat162*)(g_w_h + o)     = hA;
    *(__nv_bfloat162*)(g_w_h + o + 2) = hB;
    *(__nv_bfloat162*)(g_w_l + o)     = lA;
    *(__nv_bfloat162*)(g_w_l + o + 2) = lB;
}

// ---------------- B [N,8] -> padded [N,16] hi/lo ----------------
__global__ void cvt_b16_kernel(const float* __restrict__ B, int slot)
{
    int r = blockIdx.x * blockDim.x + threadIdx.x;
    if (r >= DIMK) return;
    size_t o = (size_t)slot * DIMK * 16 + (size_t)r * 16;
    __nv_bfloat16 z = __float2bfloat16(0.f);
    #pragma unroll
    for (int j = 0; j < 8; j++) {
        __nv_bfloat16 h, l;
        splitf(B[r * 8 + j], h, l);
        g_b16_h[o + j] = h; g_b16_l[o + j] = l;
        g_b16_h[o + 8 + j] = z; g_b16_l[o + 8 + j] = z;
    }
}

// ---------------- rank-8 projections + gates for q/k/v (16 tokens / block) ----------------
__global__ __launch_bounds__(256)
void lowrank_qkv_kernel(
    const float* __restrict__ Aq, const float* __restrict__ Ak, const float* __restrict__ Av,
    const float* __restrict__ Gq, const float* __restrict__ Gk, const float* __restrict__ Gv,
    const float* __restrict__ Go)
{
    extern __shared__ float dsm[];
    float* xs  = dsm;                 // 16*1024
    float* ms  = dsm + 16 * 1024;     // 16*1024
    float* res = dsm + 32 * 1024;     // 16*64
    int t0 = blockIdx.x * 16;
    int tid = threadIdx.x;
    int w = tid >> 5, lane = tid & 31;

    // stage 16 x/m rows into smem
    for (int it = 0; it < 16; ++it) {
        int i = tid + it * 256;       // 0..4095 float4 units
        int row = i >> 8, c4 = i & 255;
        ((float4*)xs)[i] = ((const float4*)(g_xn + (size_t)(t0 + row) * DIMK))[c4];
        ((float4*)ms)[i] = ((const float4*)(g_mn + (size_t)(t0 + row) * DIMK))[c4];
    }
    __syncthreads();

    // each warp owns 2 tokens; loop over 56 projection vectors
    int tokA = 2 * w, tokB = 2 * w + 1;
    const float* srcA;
    for (int d = 0; d < 56; ++d) {
        const float* vec;
        bool useM;
        if (d < 8)       { vec = Aq + d * DIMK;        useM = false; }
        else if (d < 16) { vec = Ak + (d - 8) * DIMK;  useM = false; }
        else if (d < 24) { vec = Av + (d - 16) * DIMK; useM = false; }
        else if (d < 32) { vec = Gq + (d - 24) * DIMK; useM = true; }
        else if (d < 40) { vec = Gk + (d - 32) * DIMK; useM = true; }
        else if (d < 48) { vec = Gv + (d - 40) * DIMK; useM = true; }
        else             { vec = Go + (d - 48) * DIMK; useM = true; }
        const float* base = useM ? ms : xs;
        const float4* ra = (const float4*)(base + tokA * DIMK);
        const float4* rb = (const float4*)(base + tokB * DIMK);
        const float4* vv = (const float4*)vec;
        float accA = 0.f, accB = 0.f;
        #pragma unroll
        for (int i = lane; i < 256; i += 32) {
            float4 vvv = vv[i];
            float4 xa = ra[i], xb = rb[i];
            accA += vvv.x*xa.x + vvv.y*xa.y + vvv.z*xa.z + vvv.w*xa.w;
            accB += vvv.x*xb.x + vvv.y*xb.y + vvv.z*xb.z + vvv.w*xb.w;
        }
        #pragma unroll
        for (int o = 16; o; o >>= 1) {
            accA += __shfl_xor_sync(0xffffffffu, accA, o);
            accB += __shfl_xor_sync(0xffffffffu, accB, o);
        }
        if (lane == 0) { res[tokA * 64 + d] = accA; res[tokB * 64 + d] = accB; }
    }
    (void)srcA;
    __syncthreads();

    // finalize: token = tid>>4, j = tid&15
    int tok = tid >> 4, j = tid & 15;
    int tg = t0 + tok;
    const float* r = res + tok * 64;
    float vq = 0.f, vk = 0.f, vv2 = 0.f;
    if (j < 8) {
        vq  = 0.25f * r[j]      * r[24 + j];
        vk  = 0.25f * r[8 + j]  * r[32 + j];
        vv2 = 0.25f * r[16 + j] * r[40 + j];
        g_go[tg * 8 + j] = r[48 + j];
    }
    __nv_bfloat16 h, l;
    splitf(vq, h, l);  g_lq_h[tg*16 + j] = h; g_lq_l[tg*16 + j] = l;
    splitf(vk, h, l);  g_lk_h[tg*16 + j] = h; g_lk_l[tg*16 + j] = l;
    splitf(vv2, h, l); g_lv_h[tg*16 + j] = h; g_lv_l[tg*16 + j] = l;
}

// ---------------- rank-8 projection for o (after attention) ----------------
__global__ void lowrank_o_kernel(const float* __restrict__ Ao)
{
    int t = blockIdx.x;
    int tid = threadIdx.x;          // 128
    int warp = tid >> 5, lane = tid & 31;
    __shared__ float res[8];
    const float4* ar = (const float4*)(g_att + (size_t)t * DIMK);
    for (int d = warp; d < 8; d += 4) {
        const float4* vec = (const float4*)(Ao + d * DIMK);
        float sacc = 0.f;
        for (int i = lane; i < DIMK / 4; i += 32) {
            float4 u = ar[i], w = vec[i];
            sacc += u.x*w.x + u.y*w.y + u.z*w.z + u.w*w.w;
        }
        #pragma unroll
        for (int o = 16; o; o >>= 1) sacc += __shfl_xor_sync(0xffffffffu, sacc, o);
        if (lane == 0) res[d] = sacc;
    }
    __syncthreads();
    if (tid < 16) {
        float vo = 0.f;
        if (tid < 8) vo = 0.25f * res[tid] * g_go[t*8 + tid];
        __nv_bfloat16 h, l;
        splitf(vo, h, l);
        g_lo_h[t*16 + tid] = h; g_lo_l[t*16 + tid] = l;
    }
}

// ---------------- HMMA split-bf16 GEMM + folded rank-8 LoRA ----------------
// C[128m x 128n] = X[128,1024]*W[128n,1024]^T + low16[128,16]*B16[128n,16]^T
// 3-term split (hi*hi + hi*lo + lo*hi) via mma.sync.m16n8k16 bf16, fp32 acc.
// 128x128x64 CTA tile, 8 warps (4m x 2n) of 32x64, cp.async double buffer.
// Smem: stage s at s*65536: Ah +0, Al +16384, Wh +32768, Wl +49152 (SW128 swizzle)
// LoRA tiles at 131072: Lh/Ll/Bh/Bl, 128 rows x 16 cols, 48B row stride.
__global__ __launch_bounds__(256, 1)
void gemm_mma_kernel(const __nv_bfloat16* __restrict__ Xh, const __nv_bfloat16* __restrict__ Xl,
                     const __nv_bfloat16* __restrict__ Wh, const __nv_bfloat16* __restrict__ Wl,
                     const __nv_bfloat16* __restrict__ Lh, const __nv_bfloat16* __restrict__ Ll,
                     const __nv_bfloat16* __restrict__ Bh, const __nv_bfloat16* __restrict__ Bl,
                     float* __restrict__ C)
{
    extern __shared__ char smem[];
    const uint32_t sb = smem_u32(smem);
    const int tid = threadIdx.x;
    const int lane = tid & 31, w = tid >> 5;
    const int wm = (w & 3) * 32, wn = (w >> 2) * 64;
    const int bm = blockIdx.y * 128, bn = blockIdx.x * 128;

    // ---- LoRA tiles -> smem (plain stores; tiny) ----
    {
        int row = tid >> 1, cs = tid & 1;
        uint32_t so = 131072u + (uint32_t)row * 48 + cs * 16;
        size_t gl = (size_t)(bm + row) * 16 + cs * 8;
        size_t gb = (size_t)(bn + row) * 16 + cs * 8;
        *(int4*)(smem + so)          = *(const int4*)(Lh + gl);
        *(int4*)(smem + so + 6144)   = *(const int4*)(Ll + gl);
        *(int4*)(smem + so + 12288)  = *(const int4*)(Bh + gb);
        *(int4*)(smem + so + 18432)  = *(const int4*)(Bl + gb);
    }

    // ---- cp.async stage loader ----
    const int r0 = tid >> 3, seg = tid & 7;
    auto load_stage = [&](int c, int s) {
        uint32_t sbase = sb + (uint32_t)s * 65536;
        #pragma unroll
        for (int j = 0; j < 4; ++j) {
            int row = r0 + j * 32;
            size_t offx = (size_t)(bm + row) * DIMK + c * 64 + seg * 8;
            size_t offw = (size_t)(bn + row) * DIMK + c * 64 + seg * 8;
            uint32_t so = sbase + swz128u((uint32_t)row * 128 + seg * 16);
            cpa16(so,          Xh + offx);
            cpa16(so + 16384,  Xl + offx);
            cpa16(so + 32768,  Wh + offw);
            cpa16(so + 49152,  Wl + offw);
        }
    };

    // ---- per-lane fragment address precompute ----
    // A (x4): rows m0-7/m8-15 klo, then khi
    uint32_t aRow[2], aXor[2];
    #pragma unroll
    for (int mt = 0; mt < 2; ++mt) {
        int rA = wm + mt * 16 + (lane & 15);
        aRow[mt] = (uint32_t)rA * 128;
        aXor[mt] = (uint32_t)((rA & 7) << 4);
    }
    const uint32_t aK = (uint32_t)((lane >> 4) << 4);
    // B (x4 = two n-tiles): lanes 0-7 ntEven klo, 8-15 ntEven khi, 16-23 ntOdd klo, 24-31 ntOdd khi
    uint32_t bRow[4], bXor[4];
    #pragma unroll
    for (int np = 0; np < 4; ++np) {
        int rB = wn + np * 16 + ((lane >> 4) & 1) * 8 + (lane & 7);
        bRow[np] = (uint32_t)rB * 128;
        bXor[np] = (uint32_t)((rB & 7) << 4);
    }
    const uint32_t bK = (uint32_t)(((lane >> 3) & 1) * 16);

    float acc[2][8][4];
    #pragma unroll
    for (int mt = 0; mt < 2; ++mt)
        #pragma unroll
        for (int nt = 0; nt < 8; ++nt)
            #pragma unroll
            for (int i = 0; i < 4; ++i) acc[mt][nt][i] = 0.f;

    // ---- compute one 64-wide K chunk from stage s ----
    auto compute = [&](int s) {
        uint32_t sbase = sb + (uint32_t)s * 65536;
        #pragma unroll
        for (int ks = 0; ks < 4; ++ks) {
            uint32_t kb = (uint32_t)ks * 32;
            uint32_t ah[2][4], al[2][4], bh[4][4], bl[4][4];
            #pragma unroll
            for (int mt = 0; mt < 2; ++mt) {
                uint32_t ad = sbase + ((aRow[mt] + kb + aK) ^ aXor[mt]);
                ldsm4(ah[mt], ad);
                ldsm4(al[mt], ad + 16384);
            }
            #pragma unroll
            for (int np = 0; np < 4; ++np) {
                uint32_t bd = sbase + 32768 + ((bRow[np] + kb + bK) ^ bXor[np]);
                ldsm4(bh[np], bd);
                ldsm4(bl[np], bd + 16384);
            }
            #pragma unroll
            for (int mt = 0; mt < 2; ++mt)
                #pragma unroll
                for (int np = 0; np < 4; ++np)
                    #pragma unroll
                    for (int hf = 0; hf < 2; ++hf) {
                        float* cc = acc[mt][np * 2 + hf];
                        mma16816(cc, ah[mt], &bh[np][hf * 2]);
                        mma16816(cc, ah[mt], &bl[np][hf * 2]);
                        mma16816(cc, al[mt], &bh[np][hf * 2]);
                    }
        }
    };

    load_stage(0, 0); CP_COMMIT();
    #pragma unroll 1
    for (int c = 0; c < 16; ++c) {
        if (c < 15) { load_stage(c + 1, (c + 1) & 1); CP_COMMIT(); CP_WAIT1(); }
        else        { CP_WAIT0(); }
        __syncthreads();
        compute(c & 1);
        __syncthreads();
    }

    // ---- LoRA k16 step (stride-48 tiles, no swizzle) ----
    {
        uint32_t lb = sb + 131072u;
        uint32_t ah[2][4], al[2][4], bh[4][4], bl[4][4];
        #pragma unroll
        for (int mt = 0; mt < 2; ++mt) {
            uint32_t rA = (uint32_t)(wm + mt * 16 + (lane & 15));
            uint32_t ad = lb + rA * 48 + aK;
            ldsm4(ah[mt], ad);
            ldsm4(al[mt], ad + 6144);
        }
        #pragma unroll
        for (int np = 0; np < 4; ++np) {
            uint32_t rB = (uint32_t)(wn + np * 16 + ((lane >> 4) & 1) * 8 + (lane & 7));
            uint32_t bd = lb + 12288 + rB * 48 + bK;
            ldsm4(bh[np], bd);
            ldsm4(bl[np], bd + 6144);
        }
        #pragma unroll
        for (int mt = 0; mt < 2; ++mt)
            #pragma unroll
            for (int np = 0; np < 4; ++np)
                #pragma unroll
                for (int hf = 0; hf < 2; ++hf) {
                    float* cc = acc[mt][np * 2 + hf];
                    mma16816(cc, ah[mt], &bh[np][hf * 2]);
                    mma16816(cc, ah[mt], &bl[np][hf * 2]);
                    mma16816(cc, al[mt], &bh[np][hf * 2]);
                }
    }

    // ---- epilogue: fp32 C ----
    #pragma unroll
    for (int mt = 0; mt < 2; ++mt) {
        int m0 = bm + wm + mt * 16 + (lane >> 2);
        #pragma unroll
        for (int nt = 0; nt < 8; ++nt) {
            int n0 = bn + wn + nt * 8 + (lane & 3) * 2;
            float2 v0 = make_float2(acc[mt][nt][0], acc[mt][nt][1]);
            float2 v1 = make_float2(acc[mt][nt][2], acc[mt][nt][3]);
            *(float2*)(C + (size_t)m0 * DIMK + n0)       = v0;
            *(float2*)(C + (size_t)(m0 + 8) * DIMK + n0) = v1;
        }
    }
}

// ---------------- flash attention, block-causal (frame=256), fp32 ----------------
__device__ __forceinline__ int swz(int row, int col4) {
    return (row << 6) + (((col4 ^ (row >> 2)) & 15) << 2);
}

__global__ __launch_bounds__(256)
void attn_kernel(const float* __restrict__ q, const float* __restrict__ k,
                 const float* __restrict__ v, float* __restrict__ o,
                 __nv_bfloat16* __restrict__ oh, __nv_bfloat16* __restrict__ ol)
{
    __shared__ float Qs[4096];
    __shared__ float KPs[4096];
    __shared__ float Vs[4096];

    int qt = 31 - (int)blockIdx.x;
    int h  = blockIdx.y;
    int b  = blockIdx.z;
    int t0 = qt << 6;
    int ntile = ((qt >> 2) + 1) << 2;
    int tid = threadIdx.x;
    int tx = tid & 15, ty = tid >> 4;
    size_t base = ((size_t)b * 2048) * DIMK + h * DHEAD;
    const float* qb = q + base;
    const float* kb = k + base;
    const float* vb = v + base;

    for (int i = tid; i < 1024; i += 256) {
        int tok = i >> 4, c4 = i & 15, dh = c4 << 2;
        float4 val = *(const float4*)(qb + (size_t)(t0 + tok) * DIMK + dh);
        int c = tok >> 2, rmod = tok & 3;
        Qs[swz(dh + 0, c) + rmod] = val.x;
        Qs[swz(dh + 1, c) + rmod] = val.y;
        Qs[swz(dh + 2, c) + rmod] = val.z;
        Qs[swz(dh + 3, c) + rmod] = val.w;
    }

    float acc[4][4];
    #pragma unroll
    for (int i = 0; i < 4; i++)
        #pragma unroll
        for (int j = 0; j < 4; j++) acc[i][j] = 0.f;
    float mreg[4] = {-1e30f, -1e30f, -1e30f, -1e30f};
    float lreg[4] = {0.f, 0.f, 0.f, 0.f};

    for (int kt = 0; kt < ntile; ++kt) {
        __syncthreads();
        const float* kp = kb + (size_t)(kt << 6) * DIMK;
        const float* vp = vb + (size_t)(kt << 6) * DIMK;
        for (int i = tid; i < 1024; i += 256) {
            int tok = i >> 4, c4 = i & 15, dh = c4 << 2;
            float4 kvv = *(const float4*)(kp + (size_t)tok * DIMK + dh);
            int c = tok >> 2, rmod = tok & 3;
            KPs[swz(dh + 0, c) + rmod] = kvv.x;
            KPs[swz(dh + 1, c) + rmod] = kvv.y;
            KPs[swz(dh + 2, c) + rmod] = kvv.z;
            KPs[swz(dh + 3, c) + rmod] = kvv.w;
            float4 vvv = *(const float4*)(vp + (size_t)tok * DIMK + dh);
            *(float4*)&Vs[(tok << 6) + dh] = vvv;
        }
        __syncthreads();

        float s[4][4];
        #pragma unroll
        for (int i = 0; i < 4; i++)
            #pragma unroll
            for (int j = 0; j < 4; j++) s[i][j] = 0.f;
        #pragma unroll 8
        for (int kk = 0; kk < 64; ++kk) {
            float qa[4], ka[4];
            *(float4*)&qa[0] = *(const float4*)&Qs[swz(kk, ty)];
            *(float4*)&ka[0] = *(const float4*)&KPs[swz(kk, tx)];
            #pragma unroll
            for (int i = 0; i < 4; i++)
                #pragma unroll
                for (int j = 0; j < 4; j++)
                    s[i][j] += qa[i] * ka[j];
        }
        __syncthreads();

        float p[4][4];
        #pragma unroll
        for (int i = 0; i < 4; i++) {
            #pragma unroll
            for (int j = 0; j < 4; j++) s[i][j] *= 0.125f;
            float rm = fmaxf(fmaxf(s[i][0], s[i][1]), fmaxf(s[i][2], s[i][3]));
            #pragma unroll
            for (int off = 8; off; off >>= 1)
                rm = fmaxf(rm, __shfl_xor_sync(0xffffffffu, rm, off));
            float mnew = fmaxf(mreg[i], rm);
            float corr = __expf(mreg[i] - mnew);
            mreg[i] = mnew;
            float ps = 0.f;
            #pragma unroll
            for (int j = 0; j < 4; j++) { p[i][j] = __expf(s[i][j] - mnew); ps += p[i][j]; }
            #pragma unroll
            for (int off = 8; off; off >>= 1)
                ps += __shfl_xor_sync(0xffffffffu, ps, off);
            lreg[i] = lreg[i] * corr + ps;
            #pragma unroll
            for (int j = 0; j < 4; j++) acc[i][j] *= corr;
        }
        #pragma unroll
        for (int i = 0; i < 4; i++)
            #pragma unroll
            for (int j = 0; j < 4; j++)
                KPs[swz((tx << 2) + j, ty) + i] = p[i][j];
        __syncthreads();

        #pragma unroll 8
        for (int kk = 0; kk < 64; ++kk) {
            float pa[4], va[4];
            *(float4*)&pa[0] = *(const float4*)&KPs[swz(kk, ty)];
            *(float4*)&va[0] = *(const float4*)&Vs[(kk << 6) + (tx << 2)];
            #pragma unroll
            for (int i = 0; i < 4; i++)
                #pragma unroll
                for (int j = 0; j < 4; j++)
                    acc[i][j] += pa[i] * va[j];
        }
    }

    #pragma unroll
    for (int i = 0; i < 4; i++) {
        float inv = 1.0f / lreg[i];
        float o0 = acc[i][0]*inv, o1 = acc[i][1]*inv, o2 = acc[i][2]*inv, o3 = acc[i][3]*inv;
        size_t e = base + (size_t)(t0 + (ty << 2) + i) * DIMK + (tx << 2);
        *(float4*)(o + e) = make_float4(o0, o1, o2, o3);
        __nv_bfloat16 h0,h1,h2,h3,l0,l1,l2,l3;
        splitf(o0,h0,l0); splitf(o1,h1,l1); splitf(o2,h2,l2); splitf(o3,h3,l3);
        __nv_bfloat162 hA; hA.x=h0; hA.y=h1;
        __nv_bfloat162 hB; hB.x=h2; hB.y=h3;
        __nv_bfloat162 lA; lA.x=l0; lA.y=l1;
        __nv_bfloat162 lB; lB.x=l2; lB.y=l3;
        *(__nv_bfloat162*)(oh + e)     = hA;
        *(__nv_bfloat162*)(oh + e + 2) = hB;
        *(__nv_bfloat162*)(ol + e)     = lA;
        *(__nv_bfloat162*)(ol + e + 2) = lB;
    }
}

// ---------------- launch ----------------
extern "C" void kernel_launch(void* const* d_in, const int* in_sizes, int n_in,
                              void* d_out, int out_size)
{
    (void)in_sizes; (void)n_in; (void)out_size;
    const float* x      = (const float*)d_in[0];
    const float* m_tok  = (const float*)d_in[1];
    const float* norm_g = (const float*)d_in[2];
    const float* norm_b = (const float*)d_in[3];
    const float* mnorm_g= (const float*)d_in[4];
    const float* mnorm_b= (const float*)d_in[5];
    const float* Wq = (const float*)d_in[6];
    const float* Aq = (const float*)d_in[7];
    const float* Bq = (const float*)d_in[8];
    const float* Gq = (const float*)d_in[9];
    const float* Wk = (const float*)d_in[10];
    const float* Ak = (const float*)d_in[11];
    const float* Bk = (const float*)d_in[12];
    const float* Gk = (const float*)d_in[13];
    const float* Wv = (const float*)d_in[14];
    const float* Av = (const float*)d_in[15];
    const float* Bv = (const float*)d_in[16];
    const float* Gv = (const float*)d_in[17];
    const float* Wo = (const float*)d_in[18];
    const float* Ao = (const float*)d_in[19];
    const float* Bo = (const float*)d_in[20];
    const float* Go = (const float*)d_in[21];
    float* out = (float*)d_out;

    float *p_xn, *p_mn, *p_q, *p_k, *p_v, *p_att;
    __nv_bfloat16 *p_xnh, *p_xnl, *p_atth, *p_attl, *p_wh, *p_wl, *p_bh, *p_bl;
    __nv_bfloat16 *p_lqh, *p_lql, *p_lkh, *p_lkl, *p_lvh, *p_lvl, *p_loh, *p_lol;
    cudaGetSymbolAddress((void**)&p_xn,  g_xn);
    cudaGetSymbolAddress((void**)&p_mn,  g_mn);
    cudaGetSymbolAddress((void**)&p_q,   g_q);
    cudaGetSymbolAddress((void**)&p_k,   g_k);
    cudaGetSymbolAddress((void**)&p_v,   g_v);
    cudaGetSymbolAddress((void**)&p_att, g_att);
    cudaGetSymbolAddress((void**)&p_xnh, g_xn_h);
    cudaGetSymbolAddress((void**)&p_xnl, g_xn_l);
    cudaGetSymbolAddress((void**)&p_atth, g_att_h);
    cudaGetSymbolAddress((void**)&p_attl, g_att_l);
    cudaGetSymbolAddress((void**)&p_wh,  g_w_h);
    cudaGetSymbolAddress((void**)&p_wl,  g_w_l);
    cudaGetSymbolAddress((void**)&p_bh,  g_b16_h);
    cudaGetSymbolAddress((void**)&p_bl,  g_b16_l);
    cudaGetSymbolAddress((void**)&p_lqh, g_lq_h);
    cudaGetSymbolAddress((void**)&p_lql, g_lq_l);
    cudaGetSymbolAddress((void**)&p_lkh, g_lk_h);
    cudaGetSymbolAddress((void**)&p_lkl, g_lk_l);
    cudaGetSymbolAddress((void**)&p_lvh, g_lv_h);
    cudaGetSymbolAddress((void**)&p_lvl, g_lv_l);
    cudaGetSymbolAddress((void**)&p_loh, g_lo_h);
    cudaGetSymbolAddress((void**)&p_lol, g_lo_l);

    const int GSMEM = 2 * 65536 + 4 * 6144;       // 152 KB
    const int LSMEM = 32 * 1024 * 4 + 16 * 64 * 4; // 135 KB
    cudaFuncSetAttribute(gemm_mma_kernel, cudaFuncAttributeMaxDynamicSharedMemorySize, GSMEM);
    cudaFuncSetAttribute(lowrank_qkv_kernel, cudaFuncAttributeMaxDynamicSharedMemorySize, LSMEM);

    // weight / B conversions (independent of x)
    cvt_w_kernel<<<1024, 256>>>(Wq, 0);
    cvt_w_kernel<<<1024, 256>>>(Wk, 1);
    cvt_w_kernel<<<1024, 256>>>(Wv, 2);
    cvt_w_kernel<<<1024, 256>>>(Wo, 3);
    cvt_b16_kernel<<<4, 256>>>(Bq, 0);
    cvt_b16_kernel<<<4, 256>>>(Bk, 1);
    cvt_b16_kernel<<<4, 256>>>(Bv, 2);
    cvt_b16_kernel<<<4, 256>>>(Bo, 3);

    ln_kernel<<<NTOK, 256>>>(x,     norm_g,  norm_b,  p_xn, p_xnh, p_xnl);
    ln_kernel<<<NTOK, 256>>>(m_tok, mnorm_g, mnorm_b, p_mn, ((__nv_bfloat16*)0), ((__nv_bfloat16*)0));
    lowrank_qkv_kernel<<<NTOK / 16, 256, LSMEM>>>(Aq, Ak, Av, Gq, Gk, Gv, Go);

    dim3 gg(8, 32);
    gemm_mma_kernel<<<gg, 256, GSMEM>>>(p_xnh, p_xnl, p_wh + 0*DIMK*DIMK, p_wl + 0*DIMK*DIMK,
                                        p_lqh, p_lql, p_bh + 0*DIMK*16, p_bl + 0*DIMK*16, p_q);
    gemm_mma_kernel<<<gg, 256, GSMEM>>>(p_xnh, p_xnl, p_wh + 1*DIMK*DIMK, p_wl + 1*DIMK*DIMK,
                                        p_lkh, p_lkl, p_bh + 1*DIMK*16, p_bl + 1*DIMK*16, p_k);
    gemm_mma_kernel<<<gg, 256, GSMEM>>>(p_xnh, p_xnl, p_wh + 2*DIMK*DIMK, p_wl + 2*DIMK*DIMK,
                                        p_lvh, p_lvl, p_bh + 2*DIMK*16, p_bl + 2*DIMK*16, p_v);

    attn_kernel<<<dim3(32, 16, 2), 256>>>(p_q, p_k, p_v, p_att, p_atth, p_attl);

    lowrank_o_kernel<<<NTOK, 128>>>(Ao);
    gemm_mma_kernel<<<gg, 256, GSMEM>>>(p_atth, p_attl, p_wh + 3*DIMK*DIMK, p_wl + 3*DIMK*DIMK,
                                        p_loh, p_lol, p_bh + 3*DIMK*16, p_bl + 3*DIMK*16, out);
}

// round 4
// speedup vs baseline: 1.4097x; 1.0919x over previous
#include <cuda_runtime.h>
#include <cuda_bf16.h>
#include <math.h>
#include <stdint.h>

#define NTOK 4096            // B*T
#define DIMK 1024
#define NHEAD 16
#define DHEAD 64

// ---------------- scratch (device globals; no allocs allowed) ----------------
__device__ float g_xn [NTOK * DIMK];
__device__ float g_mn [NTOK * DIMK];
__device__ float g_att[NTOK * DIMK];
__device__ float g_go [NTOK * 8];

__device__ __nv_bfloat16 g_xn_h [NTOK * DIMK];
__device__ __nv_bfloat16 g_xn_l [NTOK * DIMK];
__device__ __nv_bfloat16 g_q_h  [NTOK * DIMK];
__device__ __nv_bfloat16 g_q_l  [NTOK * DIMK];
__device__ __nv_bfloat16 g_k_h  [NTOK * DIMK];
__device__ __nv_bfloat16 g_k_l  [NTOK * DIMK];
__device__ __nv_bfloat16 g_v_h  [NTOK * DIMK];
__device__ __nv_bfloat16 g_v_l  [NTOK * DIMK];
__device__ __nv_bfloat16 g_att_h[NTOK * DIMK];
__device__ __nv_bfloat16 g_att_l[NTOK * DIMK];
__device__ __nv_bfloat16 g_w_h  [4 * DIMK * DIMK];
__device__ __nv_bfloat16 g_w_l  [4 * DIMK * DIMK];
__device__ __nv_bfloat16 g_b16_h[4 * DIMK * 16];
__device__ __nv_bfloat16 g_b16_l[4 * DIMK * 16];
__device__ __nv_bfloat16 g_lq_h [NTOK * 16];
__device__ __nv_bfloat16 g_lq_l [NTOK * 16];
__device__ __nv_bfloat16 g_lk_h [NTOK * 16];
__device__ __nv_bfloat16 g_lk_l [NTOK * 16];
__device__ __nv_bfloat16 g_lv_h [NTOK * 16];
__device__ __nv_bfloat16 g_lv_l [NTOK * 16];
__device__ __nv_bfloat16 g_lo_h [NTOK * 16];
__device__ __nv_bfloat16 g_lo_l [NTOK * 16];

// ---------------- helpers ----------------
__device__ __forceinline__ uint32_t smem_u32(const void* p) {
    uint32_t a;
    asm("{ .reg .u64 t; cvta.to.shared.u64 t, %1; cvt.u32.u64 %0, t; }" : "=r"(a) : "l"(p));
    return a;
}

__device__ __forceinline__ void cpa16(uint32_t s, const void* g) {
    asm volatile("cp.async.cg.shared.global [%0], [%1], 16;" :: "r"(s), "l"(g));
}
#define CP_COMMIT() asm volatile("cp.async.commit_group;" ::: "memory")
#define CP_WAIT1()  asm volatile("cp.async.wait_group 1;" ::: "memory")
#define CP_WAIT0()  asm volatile("cp.async.wait_group 0;" ::: "memory")

__device__ __forceinline__ void ldsm4(uint32_t* r, uint32_t addr) {
    asm volatile("ldmatrix.sync.aligned.m8n8.x4.shared.b16 {%0,%1,%2,%3}, [%4];"
        : "=r"(r[0]), "=r"(r[1]), "=r"(r[2]), "=r"(r[3]) : "r"(addr));
}
__device__ __forceinline__ void ldsm4t(uint32_t* r, uint32_t addr) {
    asm volatile("ldmatrix.sync.aligned.m8n8.x4.trans.shared.b16 {%0,%1,%2,%3}, [%4];"
        : "=r"(r[0]), "=r"(r[1]), "=r"(r[2]), "=r"(r[3]) : "r"(addr));
}

__device__ __forceinline__ void mma16816(float* c, const uint32_t* a, const uint32_t* b) {
    asm volatile(
        "mma.sync.aligned.m16n8k16.row.col.f32.bf16.bf16.f32 "
        "{%0,%1,%2,%3}, {%4,%5,%6,%7}, {%8,%9}, {%0,%1,%2,%3};"
        : "+f"(c[0]), "+f"(c[1]), "+f"(c[2]), "+f"(c[3])
        : "r"(a[0]), "r"(a[1]), "r"(a[2]), "r"(a[3]), "r"(b[0]), "r"(b[1]));
}

__device__ __forceinline__ uint32_t swz128u(uint32_t o) { return o ^ ((o >> 3) & 0x70); }

__device__ __forceinline__ void splitf(float x, __nv_bfloat16& h, __nv_bfloat16& l) {
    h = __float2bfloat16(x);
    l = __float2bfloat16(x - __bfloat162float(h));
}
// pack f0 (low half) and f1 (high half) to bf16x2
__device__ __forceinline__ uint32_t packbf(float f0, float f1) {
    uint32_t r;
    asm("cvt.rn.bf16x2.f32 %0, %1, %2;" : "=r"(r) : "f"(f1), "f"(f0));
    return r;
}

// ---------------- LayerNorm + optional hi/lo bf16 output ----------------
__global__ void ln_kernel(const float* __restrict__ in, const float* __restrict__ g,
                          const float* __restrict__ b, float* __restrict__ out,
                          __nv_bfloat16* __restrict__ hi, __nv_bfloat16* __restrict__ lo)
{
    int row = blockIdx.x;
    int tid = threadIdx.x;
    float4 a = ((const float4*)(in + (size_t)row * DIMK))[tid];
    float s = a.x + a.y + a.z + a.w;
    float q = a.x*a.x + a.y*a.y + a.z*a.z + a.w*a.w;
    #pragma unroll
    for (int o = 16; o; o >>= 1) {
        s += __shfl_xor_sync(0xffffffffu, s, o);
        q += __shfl_xor_sync(0xffffffffu, q, o);
    }
    __shared__ float ss[8], sq[8];
    __shared__ float s_mean, s_rstd;
    int warp = tid >> 5, lane = tid & 31;
    if (lane == 0) { ss[warp] = s; sq[warp] = q; }
    __syncthreads();
    if (tid == 0) {
        float ts = 0.f, tq = 0.f;
        #pragma unroll
        for (int i = 0; i < 8; i++) { ts += ss[i]; tq += sq[i]; }
        float mean = ts * (1.0f / DIMK);
        float var  = tq * (1.0f / DIMK) - mean * mean;
        s_mean = mean;
        s_rstd = rsqrtf(var + 1e-5f);
    }
    __syncthreads();
    float mean = s_mean, rstd = s_rstd;
    float4 gg = ((const float4*)g)[tid];
    float4 bb = ((const float4*)b)[tid];
    float4 r;
    r.x = (a.x - mean) * rstd * gg.x + bb.x;
    r.y = (a.y - mean) * rstd * gg.y + bb.y;
    r.z = (a.z - mean) * rstd * gg.z + bb.z;
    r.w = (a.w - mean) * rstd * gg.w + bb.w;
    ((float4*)(out + (size_t)row * DIMK))[tid] = r;
    if (hi) {
        __nv_bfloat16 h0,h1,h2,h3,l0,l1,l2,l3;
        splitf(r.x,h0,l0); splitf(r.y,h1,l1); splitf(r.z,h2,l2); splitf(r.w,h3,l3);
        __nv_bfloat162 hA; hA.x=h0; hA.y=h1;
        __nv_bfloat162 hB; hB.x=h2; hB.y=h3;
        __nv_bfloat162 lA; lA.x=l0; lA.y=l1;
        __nv_bfloat162 lB; lB.x=l2; lB.y=l3;
        ((__nv_bfloat162*)(hi + (size_t)row * DIMK))[tid*2]   = hA;
        ((__nv_bfloat162*)(hi + (size_t)row * DIMK))[tid*2+1] = hB;
        ((__nv_bfloat162*)(lo + (size_t)row * DIMK))[tid*2]   = lA;
        ((__nv_bfloat162*)(lo + (size_t)row * DIMK))[tid*2+1] = lB;
    }
}

// ---------------- fp32 -> hi/lo bf16 weight conversion ----------------
__global__ void cvt_w_kernel(const float* __restrict__ in, int slot)
{
    size_t i = (size_t)blockIdx.x * blockDim.x + threadIdx.x;
    float4 v = ((const float4*)in)[i];
    __nv_bfloat16 h0,h1,h2,h3,l0,l1,l2,l3;
    splitf(v.x,h0,l0); splitf(v.y,h1,l1); splitf(v.z,h2,l2); splitf(v.w,h3,l3);
    size_t o = (size_t)slot * DIMK * DIMK + i * 4;
    __nv_bfloat162 hA; hA.x=h0; hA.y=h1;
    __nv_bfloat162 hB; hB.x=h2; hB.y=h3;
    __nv_bfloat162 lA; lA.x=l0; lA.y=l1;
    __nv_bfloat162 lB; lB.x=l2; lB.y=l3;
    *(__nv_bfloat162*)(g_w_h + o)     = hA;
    *(__nv_bfloat162*)(g_w_h + o + 2) = hB;
    *(__nv_bfloat162*)(g_w_l + o)     = lA;
    *(__nv_bfloat162*)(g_w_l + o + 2) = lB;
}

// ---------------- B [N,8] -> padded [N,16] hi/lo ----------------
__global__ void cvt_b16_kernel(const float* __restrict__ B, int slot)
{
    int r = blockIdx.x * blockDim.x + threadIdx.x;
    if (r >= DIMK) return;
    size_t o = (size_t)slot * DIMK * 16 + (size_t)r * 16;
    __nv_bfloat16 z = __float2bfloat16(0.f);
    #pragma unroll
    for (int j = 0; j < 8; j++) {
        __nv_bfloat16 h, l;
        splitf(B[r * 8 + j], h, l);
        g_b16_h[o + j] = h; g_b16_l[o + j] = l;
        g_b16_h[o + 8 + j] = z; g_b16_l[o + 8 + j] = z;
    }
}

// ---------------- rank-8 projections + gates for q/k/v (16 tokens / block) ----------------
__global__ __launch_bounds__(256)
void lowrank_qkv_kernel(
    const float* __restrict__ Aq, const float* __restrict__ Ak, const float* __restrict__ Av,
    const float* __restrict__ Gq, const float* __restrict__ Gk, const float* __restrict__ Gv,
    const float* __restrict__ Go)
{
    extern __shared__ float dsm[];
    float* xs  = dsm;
    float* ms  = dsm + 16 * 1024;
    float* res = dsm + 32 * 1024;
    int t0 = blockIdx.x * 16;
    int tid = threadIdx.x;
    int w = tid >> 5, lane = tid & 31;

    for (int it = 0; it < 16; ++it) {
        int i = tid + it * 256;
        int row = i >> 8, c4 = i & 255;
        ((float4*)xs)[i] = ((const float4*)(g_xn + (size_t)(t0 + row) * DIMK))[c4];
        ((float4*)ms)[i] = ((const float4*)(g_mn + (size_t)(t0 + row) * DIMK))[c4];
    }
    __syncthreads();

    int tokA = 2 * w, tokB = 2 * w + 1;
    for (int d = 0; d < 56; ++d) {
        const float* vec;
        bool useM;
        if (d < 8)       { vec = Aq + d * DIMK;        useM = false; }
        else if (d < 16) { vec = Ak + (d - 8) * DIMK;  useM = false; }
        else if (d < 24) { vec = Av + (d - 16) * DIMK; useM = false; }
        else if (d < 32) { vec = Gq + (d - 24) * DIMK; useM = true; }
        else if (d < 40) { vec = Gk + (d - 32) * DIMK; useM = true; }
        else if (d < 48) { vec = Gv + (d - 40) * DIMK; useM = true; }
        else             { vec = Go + (d - 48) * DIMK; useM = true; }
        const float* base = useM ? ms : xs;
        const float4* ra = (const float4*)(base + tokA * DIMK);
        const float4* rb = (const float4*)(base + tokB * DIMK);
        const float4* vv = (const float4*)vec;
        float accA = 0.f, accB = 0.f;
        #pragma unroll
        for (int i = lane; i < 256; i += 32) {
            float4 vvv = vv[i];
            float4 xa = ra[i], xb = rb[i];
            accA += vvv.x*xa.x + vvv.y*xa.y + vvv.z*xa.z + vvv.w*xa.w;
            accB += vvv.x*xb.x + vvv.y*xb.y + vvv.z*xb.z + vvv.w*xb.w;
        }
        #pragma unroll
        for (int o = 16; o; o >>= 1) {
            accA += __shfl_xor_sync(0xffffffffu, accA, o);
            accB += __shfl_xor_sync(0xffffffffu, accB, o);
        }
        if (lane == 0) { res[tokA * 64 + d] = accA; res[tokB * 64 + d] = accB; }
    }
    __syncthreads();

    int tok = tid >> 4, j = tid & 15;
    int tg = t0 + tok;
    const float* r = res + tok * 64;
    float vq = 0.f, vk = 0.f, vv2 = 0.f;
    if (j < 8) {
        vq  = 0.25f * r[j]      * r[24 + j];
        vk  = 0.25f * r[8 + j]  * r[32 + j];
        vv2 = 0.25f * r[16 + j] * r[40 + j];
        g_go[tg * 8 + j] = r[48 + j];
    }
    __nv_bfloat16 h, l;
    splitf(vq, h, l);  g_lq_h[tg*16 + j] = h; g_lq_l[tg*16 + j] = l;
    splitf(vk, h, l);  g_lk_h[tg*16 + j] = h; g_lk_l[tg*16 + j] = l;
    splitf(vv2, h, l); g_lv_h[tg*16 + j] = h; g_lv_l[tg*16 + j] = l;
}

// ---------------- rank-8 projection for o (after attention) ----------------
__global__ void lowrank_o_kernel(const float* __restrict__ Ao)
{
    int t = blockIdx.x;
    int tid = threadIdx.x;
    int warp = tid >> 5, lane = tid & 31;
    __shared__ float res[8];
    const float4* ar = (const float4*)(g_att + (size_t)t * DIMK);
    for (int d = warp; d < 8; d += 4) {
        const float4* vec = (const float4*)(Ao + d * DIMK);
        float sacc = 0.f;
        for (int i = lane; i < DIMK / 4; i += 32) {
            float4 u = ar[i], w = vec[i];
            sacc += u.x*w.x + u.y*w.y + u.z*w.z + u.w*w.w;
        }
        #pragma unroll
        for (int o = 16; o; o >>= 1) sacc += __shfl_xor_sync(0xffffffffu, sacc, o);
        if (lane == 0) res[d] = sacc;
    }
    __syncthreads();
    if (tid < 16) {
        float vo = 0.f;
        if (tid < 8) vo = 0.25f * res[tid] * g_go[t*8 + tid];
        __nv_bfloat16 h, l;
        splitf(vo, h, l);
        g_lo_h[t*16 + tid] = h; g_lo_l[t*16 + tid] = l;
    }
}

// ---------------- HMMA split-bf16 GEMM + folded rank-8 LoRA ----------------
// Outputs: optional fp32 C, optional hi/lo bf16 (Ch/Cl) split of the fp32 result.
__global__ __launch_bounds__(256, 1)
void gemm_mma_kernel(const __nv_bfloat16* __restrict__ Xh, const __nv_bfloat16* __restrict__ Xl,
                     const __nv_bfloat16* __restrict__ Wh, const __nv_bfloat16* __restrict__ Wl,
                     const __nv_bfloat16* __restrict__ Lh, const __nv_bfloat16* __restrict__ Ll,
                     const __nv_bfloat16* __restrict__ Bh, const __nv_bfloat16* __restrict__ Bl,
                     float* __restrict__ C,
                     __nv_bfloat16* __restrict__ Ch, __nv_bfloat16* __restrict__ Cl)
{
    extern __shared__ char smem[];
    const uint32_t sb = smem_u32(smem);
    const int tid = threadIdx.x;
    const int lane = tid & 31, w = tid >> 5;
    const int wm = (w & 3) * 32, wn = (w >> 2) * 64;
    const int bm = blockIdx.y * 128, bn = blockIdx.x * 128;

    // LoRA tiles -> smem
    {
        int row = tid >> 1, cs = tid & 1;
        uint32_t so = 131072u + (uint32_t)row * 48 + cs * 16;
        size_t gl = (size_t)(bm + row) * 16 + cs * 8;
        size_t gb = (size_t)(bn + row) * 16 + cs * 8;
        *(int4*)(smem + so)          = *(const int4*)(Lh + gl);
        *(int4*)(smem + so + 6144)   = *(const int4*)(Ll + gl);
        *(int4*)(smem + so + 12288)  = *(const int4*)(Bh + gb);
        *(int4*)(smem + so + 18432)  = *(const int4*)(Bl + gb);
    }

    const int r0 = tid >> 3, seg = tid & 7;
    auto load_stage = [&](int c, int s) {
        uint32_t sbase = sb + (uint32_t)s * 65536;
        #pragma unroll
        for (int j = 0; j < 4; ++j) {
            int row = r0 + j * 32;
            size_t offx = (size_t)(bm + row) * DIMK + c * 64 + seg * 8;
            size_t offw = (size_t)(bn + row) * DIMK + c * 64 + seg * 8;
            uint32_t so = sbase + swz128u((uint32_t)row * 128 + seg * 16);
            cpa16(so,          Xh + offx);
            cpa16(so + 16384,  Xl + offx);
            cpa16(so + 32768,  Wh + offw);
            cpa16(so + 49152,  Wl + offw);
        }
    };

    uint32_t aRow[2], aXor[2];
    #pragma unroll
    for (int mt = 0; mt < 2; ++mt) {
        int rA = wm + mt * 16 + (lane & 15);
        aRow[mt] = (uint32_t)rA * 128;
        aXor[mt] = (uint32_t)((rA & 7) << 4);
    }
    const uint32_t aK = (uint32_t)((lane >> 4) << 4);
    uint32_t bRow[4], bXor[4];
    #pragma unroll
    for (int np = 0; np < 4; ++np) {
        int rB = wn + np * 16 + ((lane >> 4) & 1) * 8 + (lane & 7);
        bRow[np] = (uint32_t)rB * 128;
        bXor[np] = (uint32_t)((rB & 7) << 4);
    }
    const uint32_t bK = (uint32_t)(((lane >> 3) & 1) * 16);

    float acc[2][8][4];
    #pragma unroll
    for (int mt = 0; mt < 2; ++mt)
        #pragma unroll
        for (int nt = 0; nt < 8; ++nt)
            #pragma unroll
            for (int i = 0; i < 4; ++i) acc[mt][nt][i] = 0.f;

    auto compute = [&](int s) {
        uint32_t sbase = sb + (uint32_t)s * 65536;
        #pragma unroll
        for (int ks = 0; ks < 4; ++ks) {
            uint32_t kb = (uint32_t)ks * 32;
            uint32_t ah[2][4], al[2][4], bh[4][4], bl[4][4];
            #pragma unroll
            for (int mt = 0; mt < 2; ++mt) {
                uint32_t ad = sbase + ((aRow[mt] + kb + aK) ^ aXor[mt]);
                ldsm4(ah[mt], ad);
                ldsm4(al[mt], ad + 16384);
            }
            #pragma unroll
            for (int np = 0; np < 4; ++np) {
                uint32_t bd = sbase + 32768 + ((bRow[np] + kb + bK) ^ bXor[np]);
                ldsm4(bh[np], bd);
                ldsm4(bl[np], bd + 16384);
            }
            #pragma unroll
            for (int mt = 0; mt < 2; ++mt)
                #pragma unroll
                for (int np = 0; np < 4; ++np)
                    #pragma unroll
                    for (int hf = 0; hf < 2; ++hf) {
                        float* cc = acc[mt][np * 2 + hf];
                        mma16816(cc, ah[mt], &bh[np][hf * 2]);
                        mma16816(cc, ah[mt], &bl[np][hf * 2]);
                        mma16816(cc, al[mt], &bh[np][hf * 2]);
                    }
        }
    };

    load_stage(0, 0); CP_COMMIT();
    #pragma unroll 1
    for (int c = 0; c < 16; ++c) {
        if (c < 15) { load_stage(c + 1, (c + 1) & 1); CP_COMMIT(); CP_WAIT1(); }
        else        { CP_WAIT0(); }
        __syncthreads();
        compute(c & 1);
        __syncthreads();
    }

    // LoRA k16 step
    {
        uint32_t lb = sb + 131072u;
        uint32_t ah[2][4], al[2][4], bh[4][4], bl[4][4];
        #pragma unroll
        for (int mt = 0; mt < 2; ++mt) {
            uint32_t rA = (uint32_t)(wm + mt * 16 + (lane & 15));
            uint32_t ad = lb + rA * 48 + aK;
            ldsm4(ah[mt], ad);
            ldsm4(al[mt], ad + 6144);
        }
        #pragma unroll
        for (int np = 0; np < 4; ++np) {
            uint32_t rB = (uint32_t)(wn + np * 16 + ((lane >> 4) & 1) * 8 + (lane & 7));
            uint32_t bd = lb + 12288 + rB * 48 + bK;
            ldsm4(bh[np], bd);
            ldsm4(bl[np], bd + 6144);
        }
        #pragma unroll
        for (int mt = 0; mt < 2; ++mt)
            #pragma unroll
            for (int np = 0; np < 4; ++np)
                #pragma unroll
                for (int hf = 0; hf < 2; ++hf) {
                    float* cc = acc[mt][np * 2 + hf];
                    mma16816(cc, ah[mt], &bh[np][hf * 2]);
                    mma16816(cc, ah[mt], &bl[np][hf * 2]);
                    mma16816(cc, al[mt], &bh[np][hf * 2]);
                }
    }

    // epilogue: optional fp32 + optional hi/lo bf16
    #pragma unroll
    for (int mt = 0; mt < 2; ++mt) {
        int m0 = bm + wm + mt * 16 + (lane >> 2);
        #pragma unroll
        for (int nt = 0; nt < 8; ++nt) {
            int n0 = bn + wn + nt * 8 + (lane & 3) * 2;
            float* a = acc[mt][nt];
            if (C) {
                *(float2*)(C + (size_t)m0 * DIMK + n0)       = make_float2(a[0], a[1]);
                *(float2*)(C + (size_t)(m0 + 8) * DIMK + n0) = make_float2(a[2], a[3]);
            }
            if (Ch) {
                __nv_bfloat16 h0,h1,h2,h3,l0,l1,l2,l3;
                splitf(a[0],h0,l0); splitf(a[1],h1,l1);
                splitf(a[2],h2,l2); splitf(a[3],h3,l3);
                __nv_bfloat162 p0; p0.x=h0; p0.y=h1;
                __nv_bfloat162 p1; p1.x=h2; p1.y=h3;
                __nv_bfloat162 q0; q0.x=l0; q0.y=l1;
                __nv_bfloat162 q1; q1.x=l2; q1.y=l3;
                *(__nv_bfloat162*)(Ch + (size_t)m0 * DIMK + n0)       = p0;
                *(__nv_bfloat162*)(Ch + (size_t)(m0 + 8) * DIMK + n0) = p1;
                *(__nv_bfloat162*)(Cl + (size_t)m0 * DIMK + n0)       = q0;
                *(__nv_bfloat162*)(Cl + (size_t)(m0 + 8) * DIMK + n0) = q1;
            }
        }
    }
}

// ---------------- HMMA split-bf16 flash attention, block-causal (frame=256) ----------------
// 128 threads (4 warps), each warp: 16 q-rows x 64 keys x 64 dh.
// Smem: Qh 0 (8KB), Ql 8192; K/V stage s at 16384+s*32768: Kh,Kl,Vh,Vl (8KB each).
__global__ __launch_bounds__(128)
void attn_mma_kernel(const __nv_bfloat16* __restrict__ qh, const __nv_bfloat16* __restrict__ ql,
                     const __nv_bfloat16* __restrict__ kh, const __nv_bfloat16* __restrict__ kl,
                     const __nv_bfloat16* __restrict__ vh, const __nv_bfloat16* __restrict__ vl,
                     float* __restrict__ o,
                     __nv_bfloat16* __restrict__ oh, __nv_bfloat16* __restrict__ ol)
{
    extern __shared__ char smem[];
    const uint32_t sb = smem_u32(smem);
    int qt = 31 - (int)blockIdx.x;
    int h  = blockIdx.y;
    int b  = blockIdx.z;
    int t0 = qt << 6;
    int ntile = ((qt >> 2) + 1) << 2;
    int tid = threadIdx.x, lane = tid & 31, w = tid >> 5;
    size_t base = ((size_t)b * 2048) * DIMK + h * DHEAD;

    const int lrow = tid >> 1;
    const int lsegb = (tid & 1) * 4;

    // Q load (hi+lo)
    {
        size_t g = base + (size_t)(t0 + lrow) * DIMK;
        #pragma unroll
        for (int j = 0; j < 4; ++j) {
            int seg = lsegb + j;
            uint32_t so = sb + swz128u((uint32_t)lrow * 128 + seg * 16);
            cpa16(so,        qh + g + seg * 8);
            cpa16(so + 8192, ql + g + seg * 8);
        }
    }
    auto load_kv = [&](int kt, int st) {
        uint32_t sv = sb + 16384 + (uint32_t)st * 32768;
        size_t g = base + (size_t)((kt << 6) + lrow) * DIMK;
        #pragma unroll
        for (int j = 0; j < 4; ++j) {
            int seg = lsegb + j;
            uint32_t so = sv + swz128u((uint32_t)lrow * 128 + seg * 16);
            cpa16(so,         kh + g + seg * 8);
            cpa16(so + 8192,  kl + g + seg * 8);
            cpa16(so + 16384, vh + g + seg * 8);
            cpa16(so + 24576, vl + g + seg * 8);
        }
    };

    // fragment addressing
    const int rA = w * 16 + (lane & 15);
    const uint32_t qRow = (uint32_t)rA * 128;
    const uint32_t qXor = (uint32_t)((rA & 7) << 4);
    const uint32_t aK = (uint32_t)((lane >> 4) << 4);
    uint32_t kRow[4], kXor[4];
    #pragma unroll
    for (int np = 0; np < 4; ++np) {
        int rB = np * 16 + ((lane >> 4) & 1) * 8 + (lane & 7);
        kRow[np] = (uint32_t)rB * 128;
        kXor[np] = (uint32_t)((rB & 7) << 4);
    }
    const uint32_t bK = (uint32_t)(((lane >> 3) & 1) * 16);
    // V (trans) addressing
    const int keyB = ((lane >> 3) & 1) * 8 + (lane & 7);
    const int dhB  = ((lane >> 4) & 1) * 8;
    const uint32_t vXor = (uint32_t)((lane & 7) << 4);

    float accO[8][4];
    #pragma unroll
    for (int nt = 0; nt < 8; ++nt)
        #pragma unroll
        for (int i = 0; i < 4; ++i) accO[nt][i] = 0.f;
    float mreg[2] = {-1e30f, -1e30f};
    float lreg[2] = {0.f, 0.f};

    load_kv(0, 0); CP_COMMIT();

    #pragma unroll 1
    for (int kt = 0; kt < ntile; ++kt) {
        if (kt + 1 < ntile) { load_kv(kt + 1, (kt + 1) & 1); CP_COMMIT(); CP_WAIT1(); }
        else                { CP_WAIT0(); }
        __syncthreads();
        uint32_t kb = sb + 16384 + (uint32_t)(kt & 1) * 32768;
        uint32_t vb = kb + 16384;

        // S = QK^T (3-term split)
        float s[8][4];
        #pragma unroll
        for (int nt = 0; nt < 8; ++nt)
            #pragma unroll
            for (int i = 0; i < 4; ++i) s[nt][i] = 0.f;
        #pragma unroll
        for (int ks = 0; ks < 4; ++ks) {
            uint32_t kbyte = (uint32_t)ks * 32;
            uint32_t ah[4], al[4], bh[4][4], bl[4][4];
            uint32_t ad = sb + ((qRow + kbyte + aK) ^ qXor);
            ldsm4(ah, ad);
            ldsm4(al, ad + 8192);
            #pragma unroll
            for (int np = 0; np < 4; ++np) {
                uint32_t bd = kb + ((kRow[np] + kbyte + bK) ^ kXor[np]);
                ldsm4(bh[np], bd);
                ldsm4(bl[np], bd + 8192);
            }
            #pragma unroll
            for (int np = 0; np < 4; ++np)
                #pragma unroll
                for (int hf = 0; hf < 2; ++hf) {
                    float* cc = s[np * 2 + hf];
                    mma16816(cc, ah, &bh[np][hf * 2]);
                    mma16816(cc, ah, &bl[np][hf * 2]);
                    mma16816(cc, al, &bh[np][hf * 2]);
                }
        }

        // online softmax (rows r=lane>>2 and r+8; cols spread over quad)
        #pragma unroll
        for (int i = 0; i < 2; ++i) {
            float mx = -1e30f;
            #pragma unroll
            for (int nt = 0; nt < 8; ++nt) {
                s[nt][2*i]   *= 0.125f;
                s[nt][2*i+1] *= 0.125f;
                mx = fmaxf(mx, fmaxf(s[nt][2*i], s[nt][2*i+1]));
            }
            mx = fmaxf(mx, __shfl_xor_sync(0xffffffffu, mx, 1));
            mx = fmaxf(mx, __shfl_xor_sync(0xffffffffu, mx, 2));
            float mnew = fmaxf(mreg[i], mx);
            float corr = __expf(mreg[i] - mnew);
            mreg[i] = mnew;
            float rs = 0.f;
            #pragma unroll
            for (int nt = 0; nt < 8; ++nt) {
                float p0 = __expf(s[nt][2*i]   - mnew);
                float p1 = __expf(s[nt][2*i+1] - mnew);
                s[nt][2*i] = p0; s[nt][2*i+1] = p1;
                rs += p0 + p1;
            }
            rs += __shfl_xor_sync(0xffffffffu, rs, 1);
            rs += __shfl_xor_sync(0xffffffffu, rs, 2);
            lreg[i] = lreg[i] * corr + rs;
            #pragma unroll
            for (int nt = 0; nt < 8; ++nt) {
                accO[nt][2*i]   *= corr;
                accO[nt][2*i+1] *= corr;
            }
        }

        // pack P into A-frags (hi/lo split)
        uint32_t paH[4][4], paL[4][4];
        #pragma unroll
        for (int kp = 0; kp < 4; ++kp) {
            #pragma unroll
            for (int q4 = 0; q4 < 4; ++q4) {
                int nt = kp * 2 + (q4 >> 1);
                int e0 = (q4 & 1) * 2;
                float f0 = s[nt][e0], f1 = s[nt][e0 + 1];
                __nv_bfloat16 h0, l0, h1, l1;
                splitf(f0, h0, l0); splitf(f1, h1, l1);
                paH[kp][q4] = packbf(__bfloat162float(h0), __bfloat162float(h1));
                paL[kp][q4] = packbf(__bfloat162float(l0), __bfloat162float(l1));
            }
        }
        // reorder: a0=(r,klo) a1=(r+8,klo) a2=(r,khi) a3=(r+8,khi)
        // built above as q4: 0=(nt even, e0=0..1 -> row r), 1=(nt even, rows r+8), 2/3 = nt odd
        // mapping is already a0..a3 = (ntE r),(ntE r+8),(ntO r),(ntO r+8)  ✓

        // O += P V (3-term split), V via ldmatrix.trans
        #pragma unroll
        for (int kp = 0; kp < 4; ++kp) {
            uint32_t vrow = (uint32_t)(kp * 16 + keyB) * 128;
            uint32_t vbh[4][4], vbl[4][4];
            #pragma unroll
            for (int np = 0; np < 4; ++np) {
                uint32_t bd = vb + ((vrow + (uint32_t)(np * 16 + dhB) * 2) ^ vXor);
                ldsm4t(vbh[np], bd);
                ldsm4t(vbl[np], bd + 8192);
            }
            #pragma unroll
            for (int np = 0; np < 4; ++np)
                #pragma unroll
                for (int hf = 0; hf < 2; ++hf) {
                    float* cc = accO[np * 2 + hf];
                    mma16816(cc, paH[kp], &vbh[np][hf * 2]);
                    mma16816(cc, paH[kp], &vbl[np][hf * 2]);
                    mma16816(cc, paL[kp], &vbh[np][hf * 2]);
                }
        }
        __syncthreads();
    }

    // epilogue
    #pragma unroll
    for (int i = 0; i < 2; ++i) {
        float inv = 1.0f / lreg[i];
        int row = t0 + w * 16 + (lane >> 2) + i * 8;
        size_t rb = base + (size_t)row * DIMK;
        #pragma unroll
        for (int nt = 0; nt < 8; ++nt) {
            int col = nt * 8 + (lane & 3) * 2;
            float f0 = accO[nt][2*i] * inv, f1 = accO[nt][2*i+1] * inv;
            *(float2*)(o + rb + col) = make_float2(f0, f1);
            __nv_bfloat16 h0,l0,h1,l1;
            splitf(f0,h0,l0); splitf(f1,h1,l1);
            __nv_bfloat162 hp; hp.x=h0; hp.y=h1;
            __nv_bfloat162 lp; lp.x=l0; lp.y=l1;
            *(__nv_bfloat162*)(oh + rb + col) = hp;
            *(__nv_bfloat162*)(ol + rb + col) = lp;
        }
    }
}

// ---------------- launch ----------------
extern "C" void kernel_launch(void* const* d_in, const int* in_sizes, int n_in,
                              void* d_out, int out_size)
{
    (void)in_sizes; (void)n_in; (void)out_size;
    const float* x      = (const float*)d_in[0];
    const float* m_tok  = (const float*)d_in[1];
    const float* norm_g = (const float*)d_in[2];
    const float* norm_b = (const float*)d_in[3];
    const float* mnorm_g= (const float*)d_in[4];
    const float* mnorm_b= (const float*)d_in[5];
    const float* Wq = (const float*)d_in[6];
    const float* Aq = (const float*)d_in[7];
    const float* Bq = (const float*)d_in[8];
    const float* Gq = (const float*)d_in[9];
    const float* Wk = (const float*)d_in[10];
    const float* Ak = (const float*)d_in[11];
    const float* Bk = (const float*)d_in[12];
    const float* Gk = (const float*)d_in[13];
    const float* Wv = (const float*)d_in[14];
    const float* Av = (const float*)d_in[15];
    const float* Bv = (const float*)d_in[16];
    const float* Gv = (const float*)d_in[17];
    const float* Wo = (const float*)d_in[18];
    const float* Ao = (const float*)d_in[19];
    const float* Bo = (const float*)d_in[20];
    const float* Go = (const float*)d_in[21];
    float* out = (float*)d_out;

    float *p_xn, *p_mn, *p_att;
    __nv_bfloat16 *p_xnh, *p_xnl, *p_atth, *p_attl, *p_wh, *p_wl, *p_bh, *p_bl;
    __nv_bfloat16 *p_qh, *p_ql, *p_kh, *p_kl, *p_vh, *p_vl;
    __nv_bfloat16 *p_lqh, *p_lql, *p_lkh, *p_lkl, *p_lvh, *p_lvl, *p_loh, *p_lol;
    cudaGetSymbolAddress((void**)&p_xn,  g_xn);
    cudaGetSymbolAddress((void**)&p_mn,  g_mn);
    cudaGetSymbolAddress((void**)&p_att, g_att);
    cudaGetSymbolAddress((void**)&p_xnh, g_xn_h);
    cudaGetSymbolAddress((void**)&p_xnl, g_xn_l);
    cudaGetSymbolAddress((void**)&p_qh,  g_q_h);
    cudaGetSymbolAddress((void**)&p_ql,  g_q_l);
    cudaGetSymbolAddress((void**)&p_kh,  g_k_h);
    cudaGetSymbolAddress((void**)&p_kl,  g_k_l);
    cudaGetSymbolAddress((void**)&p_vh,  g_v_h);
    cudaGetSymbolAddress((void**)&p_vl,  g_v_l);
    cudaGetSymbolAddress((void**)&p_atth, g_att_h);
    cudaGetSymbolAddress((void**)&p_attl, g_att_l);
    cudaGetSymbolAddress((void**)&p_wh,  g_w_h);
    cudaGetSymbolAddress((void**)&p_wl,  g_w_l);
    cudaGetSymbolAddress((void**)&p_bh,  g_b16_h);
    cudaGetSymbolAddress((void**)&p_bl,  g_b16_l);
    cudaGetSymbolAddress((void**)&p_lqh, g_lq_h);
    cudaGetSymbolAddress((void**)&p_lql, g_lq_l);
    cudaGetSymbolAddress((void**)&p_lkh, g_lk_h);
    cudaGetSymbolAddress((void**)&p_lkl, g_lk_l);
    cudaGetSymbolAddress((void**)&p_lvh, g_lv_h);
    cudaGetSymbolAddress((void**)&p_lvl, g_lv_l);
    cudaGetSymbolAddress((void**)&p_loh, g_lo_h);
    cudaGetSymbolAddress((void**)&p_lol, g_lo_l);

    const int GSMEM = 2 * 65536 + 4 * 6144;        // 152 KB
    const int LSMEM = 32 * 1024 * 4 + 16 * 64 * 4; // 135 KB
    const int ASMEM = 16384 + 2 * 32768;           // 80 KB
    cudaFuncSetAttribute(gemm_mma_kernel, cudaFuncAttributeMaxDynamicSharedMemorySize, GSMEM);
    cudaFuncSetAttribute(lowrank_qkv_kernel, cudaFuncAttributeMaxDynamicSharedMemorySize, LSMEM);
    cudaFuncSetAttribute(attn_mma_kernel, cudaFuncAttributeMaxDynamicSharedMemorySize, ASMEM);

    cvt_w_kernel<<<1024, 256>>>(Wq, 0);
    cvt_w_kernel<<<1024, 256>>>(Wk, 1);
    cvt_w_kernel<<<1024, 256>>>(Wv, 2);
    cvt_w_kernel<<<1024, 256>>>(Wo, 3);
    cvt_b16_kernel<<<4, 256>>>(Bq, 0);
    cvt_b16_kernel<<<4, 256>>>(Bk, 1);
    cvt_b16_kernel<<<4, 256>>>(Bv, 2);
    cvt_b16_kernel<<<4, 256>>>(Bo, 3);

    ln_kernel<<<NTOK, 256>>>(x,     norm_g,  norm_b,  p_xn, p_xnh, p_xnl);
    ln_kernel<<<NTOK, 256>>>(m_tok, mnorm_g, mnorm_b, p_mn, ((__nv_bfloat16*)0), ((__nv_bfloat16*)0));
    lowrank_qkv_kernel<<<NTOK / 16, 256, LSMEM>>>(Aq, Ak, Av, Gq, Gk, Gv, Go);

    dim3 gg(8, 32);
    gemm_mma_kernel<<<gg, 256, GSMEM>>>(p_xnh, p_xnl, p_wh + 0*DIMK*DIMK, p_wl + 0*DIMK*DIMK,
                                        p_lqh, p_lql, p_bh + 0*DIMK*16, p_bl + 0*DIMK*16,
                                        (float*)0, p_qh, p_ql);
    gemm_mma_kernel<<<gg, 256, GSMEM>>>(p_xnh, p_xnl, p_wh + 1*DIMK*DIMK, p_wl + 1*DIMK*DIMK,
                                        p_lkh, p_lkl, p_bh + 1*DIMK*16, p_bl + 1*DIMK*16,
                                        (float*)0, p_kh, p_kl);
    gemm_mma_kernel<<<gg, 256, GSMEM>>>(p_xnh, p_xnl, p_wh + 2*DIMK*DIMK, p_wl + 2*DIMK*DIMK,
                                        p_lvh, p_lvl, p_bh + 2*DIMK*16, p_bl + 2*DIMK*16,
                                        (float*)0, p_vh, p_vl);

    attn_mma_kernel<<<dim3(32, 16, 2), 128, ASMEM>>>(p_qh, p_ql, p_kh, p_kl, p_vh, p_vl,
                                                     p_att, p_atth, p_attl);

    lowrank_o_kernel<<<NTOK, 128>>>(Ao);
    gemm_mma_kernel<<<gg, 256, GSMEM>>>(p_atth, p_attl, p_wh + 3*DIMK*DIMK, p_wl + 3*DIMK*DIMK,
                                        p_loh, p_lol, p_bh + 3*DIMK*16, p_bl + 3*DIMK*16,
                                        out, (__nv_bfloat16*)0, (__nv_bfloat16*)0);
}

// round 5
// speedup vs baseline: 2.4403x; 1.7311x over previous
#include <cuda_runtime.h>
#include <cuda_bf16.h>
#include <math.h>
#include <stdint.h>

#define NTOK 4096            // B*T
#define DIMK 1024
#define NHEAD 16
#define DHEAD 64

// ---------------- scratch (device globals; no allocs allowed) ----------------
__device__ float g_xn [NTOK * DIMK];
__device__ float g_mn [NTOK * DIMK];
__device__ float g_att[NTOK * DIMK];
__device__ float g_go [NTOK * 8];

__device__ __nv_bfloat16 g_xn_h [NTOK * DIMK];
__device__ __nv_bfloat16 g_xn_l [NTOK * DIMK];
__device__ __nv_bfloat16 g_q_h  [NTOK * DIMK];
__device__ __nv_bfloat16 g_q_l  [NTOK * DIMK];
__device__ __nv_bfloat16 g_k_h  [NTOK * DIMK];
__device__ __nv_bfloat16 g_k_l  [NTOK * DIMK];
__device__ __nv_bfloat16 g_v_h  [NTOK * DIMK];
__device__ __nv_bfloat16 g_v_l  [NTOK * DIMK];
__device__ __nv_bfloat16 g_att_h[NTOK * DIMK];
__device__ __nv_bfloat16 g_att_l[NTOK * DIMK];
__device__ __nv_bfloat16 g_w_h  [4 * DIMK * DIMK];
__device__ __nv_bfloat16 g_w_l  [4 * DIMK * DIMK];
__device__ __nv_bfloat16 g_b16_h[4 * DIMK * 16];
__device__ __nv_bfloat16 g_b16_l[4 * DIMK * 16];
__device__ __nv_bfloat16 g_lq_h [NTOK * 16];
__device__ __nv_bfloat16 g_lq_l [NTOK * 16];
__device__ __nv_bfloat16 g_lk_h [NTOK * 16];
__device__ __nv_bfloat16 g_lk_l [NTOK * 16];
__device__ __nv_bfloat16 g_lv_h [NTOK * 16];
__device__ __nv_bfloat16 g_lv_l [NTOK * 16];
__device__ __nv_bfloat16 g_lo_h [NTOK * 16];
__device__ __nv_bfloat16 g_lo_l [NTOK * 16];

// ---------------- helpers ----------------
__device__ __forceinline__ uint32_t smem_u32(const void* p) {
    uint32_t a;
    asm("{ .reg .u64 t; cvta.to.shared.u64 t, %1; cvt.u32.u64 %0, t; }" : "=r"(a) : "l"(p));
    return a;
}

__device__ __forceinline__ void cpa16(uint32_t s, const void* g) {
    asm volatile("cp.async.cg.shared.global [%0], [%1], 16;" :: "r"(s), "l"(g));
}
#define CP_COMMIT() asm volatile("cp.async.commit_group;" ::: "memory")
#define CP_WAIT1()  asm volatile("cp.async.wait_group 1;" ::: "memory")
#define CP_WAIT0()  asm volatile("cp.async.wait_group 0;" ::: "memory")

__device__ __forceinline__ void ldsm4(uint32_t* r, uint32_t addr) {
    asm volatile("ldmatrix.sync.aligned.m8n8.x4.shared.b16 {%0,%1,%2,%3}, [%4];"
        : "=r"(r[0]), "=r"(r[1]), "=r"(r[2]), "=r"(r[3]) : "r"(addr));
}
__device__ __forceinline__ void ldsm4t(uint32_t* r, uint32_t addr) {
    asm volatile("ldmatrix.sync.aligned.m8n8.x4.trans.shared.b16 {%0,%1,%2,%3}, [%4];"
        : "=r"(r[0]), "=r"(r[1]), "=r"(r[2]), "=r"(r[3]) : "r"(addr));
}

__device__ __forceinline__ void mma16816(float* c, const uint32_t* a, const uint32_t* b) {
    asm volatile(
        "mma.sync.aligned.m16n8k16.row.col.f32.bf16.bf16.f32 "
        "{%0,%1,%2,%3}, {%4,%5,%6,%7}, {%8,%9}, {%0,%1,%2,%3};"
        : "+f"(c[0]), "+f"(c[1]), "+f"(c[2]), "+f"(c[3])
        : "r"(a[0]), "r"(a[1]), "r"(a[2]), "r"(a[3]), "r"(b[0]), "r"(b[1]));
}

__device__ __forceinline__ uint32_t swz128u(uint32_t o) { return o ^ ((o >> 3) & 0x70); }

__device__ __forceinline__ void splitf(float x, __nv_bfloat16& h, __nv_bfloat16& l) {
    h = __float2bfloat16(x);
    l = __float2bfloat16(x - __bfloat162float(h));
}
// pack f0 (low half) and f1 (high half) to bf16x2 (round-to-nearest)
__device__ __forceinline__ uint32_t packbf(float f0, float f1) {
    uint32_t r;
    asm("cvt.rn.bf16x2.f32 %0, %1, %2;" : "=r"(r) : "f"(f1), "f"(f0));
    return r;
}
// fast pair split: returns hi pair, lo pair
__device__ __forceinline__ void split2(float f0, float f1, uint32_t& hp, uint32_t& lp) {
    hp = packbf(f0, f1);
    float h0 = __uint_as_float(hp << 16);
    float h1 = __uint_as_float(hp & 0xffff0000u);
    lp = packbf(f0 - h0, f1 - h1);
}

// ---------------- LayerNorm + optional hi/lo bf16 output ----------------
__global__ void ln_kernel(const float* __restrict__ in, const float* __restrict__ g,
                          const float* __restrict__ b, float* __restrict__ out,
                          __nv_bfloat16* __restrict__ hi, __nv_bfloat16* __restrict__ lo)
{
    int row = blockIdx.x;
    int tid = threadIdx.x;
    float4 a = ((const float4*)(in + (size_t)row * DIMK))[tid];
    float s = a.x + a.y + a.z + a.w;
    float q = a.x*a.x + a.y*a.y + a.z*a.z + a.w*a.w;
    #pragma unroll
    for (int o = 16; o; o >>= 1) {
        s += __shfl_xor_sync(0xffffffffu, s, o);
        q += __shfl_xor_sync(0xffffffffu, q, o);
    }
    __shared__ float ss[8], sq[8];
    __shared__ float s_mean, s_rstd;
    int warp = tid >> 5, lane = tid & 31;
    if (lane == 0) { ss[warp] = s; sq[warp] = q; }
    __syncthreads();
    if (tid == 0) {
        float ts = 0.f, tq = 0.f;
        #pragma unroll
        for (int i = 0; i < 8; i++) { ts += ss[i]; tq += sq[i]; }
        float mean = ts * (1.0f / DIMK);
        float var  = tq * (1.0f / DIMK) - mean * mean;
        s_mean = mean;
        s_rstd = rsqrtf(var + 1e-5f);
    }
    __syncthreads();
    float mean = s_mean, rstd = s_rstd;
    float4 gg = ((const float4*)g)[tid];
    float4 bb = ((const float4*)b)[tid];
    float4 r;
    r.x = (a.x - mean) * rstd * gg.x + bb.x;
    r.y = (a.y - mean) * rstd * gg.y + bb.y;
    r.z = (a.z - mean) * rstd * gg.z + bb.z;
    r.w = (a.w - mean) * rstd * gg.w + bb.w;
    ((float4*)(out + (size_t)row * DIMK))[tid] = r;
    if (hi) {
        uint32_t h0, l0, h1, l1;
        split2(r.x, r.y, h0, l0);
        split2(r.z, r.w, h1, l1);
        ((uint32_t*)(hi + (size_t)row * DIMK))[tid*2]   = h0;
        ((uint32_t*)(hi + (size_t)row * DIMK))[tid*2+1] = h1;
        ((uint32_t*)(lo + (size_t)row * DIMK))[tid*2]   = l0;
        ((uint32_t*)(lo + (size_t)row * DIMK))[tid*2+1] = l1;
    }
}

// ---------------- fp32 -> hi/lo bf16 weight conversion (all 4 slots, one launch) ----------------
__global__ void cvt_w4_kernel(const float* __restrict__ w0, const float* __restrict__ w1,
                              const float* __restrict__ w2, const float* __restrict__ w3)
{
    int slot = blockIdx.y;
    const float* in = (slot == 0) ? w0 : (slot == 1) ? w1 : (slot == 2) ? w2 : w3;
    size_t i = (size_t)blockIdx.x * blockDim.x + threadIdx.x;
    float4 v = ((const float4*)in)[i];
    uint32_t hA, lA, hB, lB;
    split2(v.x, v.y, hA, lA);
    split2(v.z, v.w, hB, lB);
    size_t o = (size_t)slot * DIMK * DIMK + i * 4;
    *(uint32_t*)(g_w_h + o)     = hA;
    *(uint32_t*)(g_w_h + o + 2) = hB;
    *(uint32_t*)(g_w_l + o)     = lA;
    *(uint32_t*)(g_w_l + o + 2) = lB;
}

// ---------------- B [N,8] -> padded [N,16] hi/lo (all 4 slots) ----------------
__global__ void cvt_b4_kernel(const float* __restrict__ b0, const float* __restrict__ b1,
                              const float* __restrict__ b2, const float* __restrict__ b3)
{
    int slot = blockIdx.y;
    const float* B = (slot == 0) ? b0 : (slot == 1) ? b1 : (slot == 2) ? b2 : b3;
    int r = blockIdx.x * blockDim.x + threadIdx.x;
    if (r >= DIMK) return;
    size_t o = (size_t)slot * DIMK * 16 + (size_t)r * 16;
    __nv_bfloat16 z = __float2bfloat16(0.f);
    #pragma unroll
    for (int j = 0; j < 8; j++) {
        __nv_bfloat16 h, l;
        splitf(B[r * 8 + j], h, l);
        g_b16_h[o + j] = h; g_b16_l[o + j] = l;
        g_b16_h[o + 8 + j] = z; g_b16_l[o + 8 + j] = z;
    }
}

// ---------------- rank-8 projections + gates for q/k/v (16 tokens / block) ----------------
__global__ __launch_bounds__(256)
void lowrank_qkv_kernel(
    const float* __restrict__ Aq, const float* __restrict__ Ak, const float* __restrict__ Av,
    const float* __restrict__ Gq, const float* __restrict__ Gk, const float* __restrict__ Gv,
    const float* __restrict__ Go)
{
    extern __shared__ float dsm[];
    float* xs  = dsm;
    float* ms  = dsm + 16 * 1024;
    float* res = dsm + 32 * 1024;
    int t0 = blockIdx.x * 16;
    int tid = threadIdx.x;
    int w = tid >> 5, lane = tid & 31;

    for (int it = 0; it < 16; ++it) {
        int i = tid + it * 256;
        int row = i >> 8, c4 = i & 255;
        ((float4*)xs)[i] = ((const float4*)(g_xn + (size_t)(t0 + row) * DIMK))[c4];
        ((float4*)ms)[i] = ((const float4*)(g_mn + (size_t)(t0 + row) * DIMK))[c4];
    }
    __syncthreads();

    int tokA = 2 * w, tokB = 2 * w + 1;
    for (int d = 0; d < 56; ++d) {
        const float* vec;
        bool useM;
        if (d < 8)       { vec = Aq + d * DIMK;        useM = false; }
        else if (d < 16) { vec = Ak + (d - 8) * DIMK;  useM = false; }
        else if (d < 24) { vec = Av + (d - 16) * DIMK; useM = false; }
        else if (d < 32) { vec = Gq + (d - 24) * DIMK; useM = true; }
        else if (d < 40) { vec = Gk + (d - 32) * DIMK; useM = true; }
        else if (d < 48) { vec = Gv + (d - 40) * DIMK; useM = true; }
        else             { vec = Go + (d - 48) * DIMK; useM = true; }
        const float* base = useM ? ms : xs;
        const float4* ra = (const float4*)(base + tokA * DIMK);
        const float4* rb = (const float4*)(base + tokB * DIMK);
        const float4* vv = (const float4*)vec;
        float accA = 0.f, accB = 0.f;
        #pragma unroll
        for (int i = lane; i < 256; i += 32) {
            float4 vvv = vv[i];
            float4 xa = ra[i], xb = rb[i];
            accA += vvv.x*xa.x + vvv.y*xa.y + vvv.z*xa.z + vvv.w*xa.w;
            accB += vvv.x*xb.x + vvv.y*xb.y + vvv.z*xb.z + vvv.w*xb.w;
        }
        #pragma unroll
        for (int o = 16; o; o >>= 1) {
            accA += __shfl_xor_sync(0xffffffffu, accA, o);
            accB += __shfl_xor_sync(0xffffffffu, accB, o);
        }
        if (lane == 0) { res[tokA * 64 + d] = accA; res[tokB * 64 + d] = accB; }
    }
    __syncthreads();

    int tok = tid >> 4, j = tid & 15;
    int tg = t0 + tok;
    const float* r = res + tok * 64;
    float vq = 0.f, vk = 0.f, vv2 = 0.f;
    if (j < 8) {
        vq  = 0.25f * r[j]      * r[24 + j];
        vk  = 0.25f * r[8 + j]  * r[32 + j];
        vv2 = 0.25f * r[16 + j] * r[40 + j];
        g_go[tg * 8 + j] = r[48 + j];
    }
    __nv_bfloat16 h, l;
    splitf(vq, h, l);  g_lq_h[tg*16 + j] = h; g_lq_l[tg*16 + j] = l;
    splitf(vk, h, l);  g_lk_h[tg*16 + j] = h; g_lk_l[tg*16 + j] = l;
    splitf(vv2, h, l); g_lv_h[tg*16 + j] = h; g_lv_l[tg*16 + j] = l;
}

// ---------------- rank-8 projection for o (after attention) ----------------
__global__ void lowrank_o_kernel(const float* __restrict__ Ao)
{
    int t = blockIdx.x;
    int tid = threadIdx.x;
    int warp = tid >> 5, lane = tid & 31;
    __shared__ float res[8];
    const float4* ar = (const float4*)(g_att + (size_t)t * DIMK);
    for (int d = warp; d < 8; d += 4) {
        const float4* vec = (const float4*)(Ao + d * DIMK);
        float sacc = 0.f;
        for (int i = lane; i < DIMK / 4; i += 32) {
            float4 u = ar[i], w = vec[i];
            sacc += u.x*w.x + u.y*w.y + u.z*w.z + u.w*w.w;
        }
        #pragma unroll
        for (int o = 16; o; o >>= 1) sacc += __shfl_xor_sync(0xffffffffu, sacc, o);
        if (lane == 0) res[d] = sacc;
    }
    __syncthreads();
    if (tid < 16) {
        float vo = 0.f;
        if (tid < 8) vo = 0.25f * res[tid] * g_go[t*8 + tid];
        __nv_bfloat16 h, l;
        splitf(vo, h, l);
        g_lo_h[t*16 + tid] = h; g_lo_l[t*16 + tid] = l;
    }
}

// ---------------- HMMA split-bf16 GEMM body + folded rank-8 LoRA ----------------
__device__ __forceinline__
void gemm_body(char* smem,
               const __nv_bfloat16* __restrict__ Xh, const __nv_bfloat16* __restrict__ Xl,
               const __nv_bfloat16* __restrict__ Wh, const __nv_bfloat16* __restrict__ Wl,
               const __nv_bfloat16* __restrict__ Lh, const __nv_bfloat16* __restrict__ Ll,
               const __nv_bfloat16* __restrict__ Bh, const __nv_bfloat16* __restrict__ Bl,
               float* __restrict__ C,
               __nv_bfloat16* __restrict__ Ch, __nv_bfloat16* __restrict__ Cl)
{
    const uint32_t sb = smem_u32(smem);
    const int tid = threadIdx.x;
    const int lane = tid & 31, w = tid >> 5;
    const int wm = (w & 3) * 32, wn = (w >> 2) * 64;
    const int bm = blockIdx.y * 128, bn = blockIdx.x * 128;

    // LoRA tiles -> smem
    {
        int row = tid >> 1, cs = tid & 1;
        uint32_t so = 131072u + (uint32_t)row * 48 + cs * 16;
        size_t gl = (size_t)(bm + row) * 16 + cs * 8;
        size_t gb = (size_t)(bn + row) * 16 + cs * 8;
        *(int4*)(smem + so)          = *(const int4*)(Lh + gl);
        *(int4*)(smem + so + 6144)   = *(const int4*)(Ll + gl);
        *(int4*)(smem + so + 12288)  = *(const int4*)(Bh + gb);
        *(int4*)(smem + so + 18432)  = *(const int4*)(Bl + gb);
    }

    const int r0 = tid >> 3, seg = tid & 7;
    auto load_stage = [&](int c, int s) {
        uint32_t sbase = sb + (uint32_t)s * 65536;
        #pragma unroll
        for (int j = 0; j < 4; ++j) {
            int row = r0 + j * 32;
            size_t offx = (size_t)(bm + row) * DIMK + c * 64 + seg * 8;
            size_t offw = (size_t)(bn + row) * DIMK + c * 64 + seg * 8;
            uint32_t so = sbase + swz128u((uint32_t)row * 128 + seg * 16);
            cpa16(so,          Xh + offx);
            cpa16(so + 16384,  Xl + offx);
            cpa16(so + 32768,  Wh + offw);
            cpa16(so + 49152,  Wl + offw);
        }
    };

    uint32_t aRow[2], aXor[2];
    #pragma unroll
    for (int mt = 0; mt < 2; ++mt) {
        int rA = wm + mt * 16 + (lane & 15);
        aRow[mt] = (uint32_t)rA * 128;
        aXor[mt] = (uint32_t)((rA & 7) << 4);
    }
    const uint32_t aK = (uint32_t)((lane >> 4) << 4);
    uint32_t bRow[4], bXor[4];
    #pragma unroll
    for (int np = 0; np < 4; ++np) {
        int rB = wn + np * 16 + ((lane >> 4) & 1) * 8 + (lane & 7);
        bRow[np] = (uint32_t)rB * 128;
        bXor[np] = (uint32_t)((rB & 7) << 4);
    }
    const uint32_t bK = (uint32_t)(((lane >> 3) & 1) * 16);

    float acc[2][8][4];
    #pragma unroll
    for (int mt = 0; mt < 2; ++mt)
        #pragma unroll
        for (int nt = 0; nt < 8; ++nt)
            #pragma unroll
            for (int i = 0; i < 4; ++i) acc[mt][nt][i] = 0.f;

    auto compute = [&](int s) {
        uint32_t sbase = sb + (uint32_t)s * 65536;
        #pragma unroll
        for (int ks = 0; ks < 4; ++ks) {
            uint32_t kb = (uint32_t)ks * 32;
            uint32_t ah[2][4], al[2][4], bh[4][4], bl[4][4];
            #pragma unroll
            for (int mt = 0; mt < 2; ++mt) {
                uint32_t ad = sbase + ((aRow[mt] + kb + aK) ^ aXor[mt]);
                ldsm4(ah[mt], ad);
                ldsm4(al[mt], ad + 16384);
            }
            #pragma unroll
            for (int np = 0; np < 4; ++np) {
                uint32_t bd = sbase + 32768 + ((bRow[np] + kb + bK) ^ bXor[np]);
                ldsm4(bh[np], bd);
                ldsm4(bl[np], bd + 16384);
            }
            #pragma unroll
            for (int mt = 0; mt < 2; ++mt)
                #pragma unroll
                for (int np = 0; np < 4; ++np)
                    #pragma unroll
                    for (int hf = 0; hf < 2; ++hf) {
                        float* cc = acc[mt][np * 2 + hf];
                        mma16816(cc, ah[mt], &bh[np][hf * 2]);
                        mma16816(cc, ah[mt], &bl[np][hf * 2]);
                        mma16816(cc, al[mt], &bh[np][hf * 2]);
                    }
        }
    };

    load_stage(0, 0); CP_COMMIT();
    #pragma unroll 1
    for (int c = 0; c < 16; ++c) {
        if (c < 15) { load_stage(c + 1, (c + 1) & 1); CP_COMMIT(); CP_WAIT1(); }
        else        { CP_WAIT0(); }
        __syncthreads();
        compute(c & 1);
        __syncthreads();
    }

    // LoRA k16 step
    {
        uint32_t lb = sb + 131072u;
        uint32_t ah[2][4], al[2][4], bh[4][4], bl[4][4];
        #pragma unroll
        for (int mt = 0; mt < 2; ++mt) {
            uint32_t rA = (uint32_t)(wm + mt * 16 + (lane & 15));
            uint32_t ad = lb + rA * 48 + aK;
            ldsm4(ah[mt], ad);
            ldsm4(al[mt], ad + 6144);
        }
        #pragma unroll
        for (int np = 0; np < 4; ++np) {
            uint32_t rB = (uint32_t)(wn + np * 16 + ((lane >> 4) & 1) * 8 + (lane & 7));
            uint32_t bd = lb + 12288 + rB * 48 + bK;
            ldsm4(bh[np], bd);
            ldsm4(bl[np], bd + 6144);
        }
        #pragma unroll
        for (int mt = 0; mt < 2; ++mt)
            #pragma unroll
            for (int np = 0; np < 4; ++np)
                #pragma unroll
                for (int hf = 0; hf < 2; ++hf) {
                    float* cc = acc[mt][np * 2 + hf];
                    mma16816(cc, ah[mt], &bh[np][hf * 2]);
                    mma16816(cc, ah[mt], &bl[np][hf * 2]);
                    mma16816(cc, al[mt], &bh[np][hf * 2]);
                }
    }

    // epilogue
    #pragma unroll
    for (int mt = 0; mt < 2; ++mt) {
        int m0 = bm + wm + mt * 16 + (lane >> 2);
        #pragma unroll
        for (int nt = 0; nt < 8; ++nt) {
            int n0 = bn + wn + nt * 8 + (lane & 3) * 2;
            float* a = acc[mt][nt];
            if (C) {
                *(float2*)(C + (size_t)m0 * DIMK + n0)       = make_float2(a[0], a[1]);
                *(float2*)(C + (size_t)(m0 + 8) * DIMK + n0) = make_float2(a[2], a[3]);
            }
            if (Ch) {
                uint32_t hp0, lp0, hp1, lp1;
                split2(a[0], a[1], hp0, lp0);
                split2(a[2], a[3], hp1, lp1);
                *(uint32_t*)(Ch + (size_t)m0 * DIMK + n0)       = hp0;
                *(uint32_t*)(Ch + (size_t)(m0 + 8) * DIMK + n0) = hp1;
                *(uint32_t*)(Cl + (size_t)m0 * DIMK + n0)       = lp0;
                *(uint32_t*)(Cl + (size_t)(m0 + 8) * DIMK + n0) = lp1;
            }
        }
    }
}

// fused q/k/v projection: blockIdx.z selects slot
__global__ __launch_bounds__(256, 1)
void gemm_qkv_kernel()
{
    extern __shared__ char smem[];
    int z = blockIdx.z;
    const __nv_bfloat16 *Lh, *Ll;
    __nv_bfloat16 *Ch, *Cl;
    if (z == 0)      { Lh = g_lq_h; Ll = g_lq_l; Ch = g_q_h; Cl = g_q_l; }
    else if (z == 1) { Lh = g_lk_h; Ll = g_lk_l; Ch = g_k_h; Cl = g_k_l; }
    else             { Lh = g_lv_h; Ll = g_lv_l; Ch = g_v_h; Cl = g_v_l; }
    gemm_body(smem, g_xn_h, g_xn_l,
              g_w_h + (size_t)z * DIMK * DIMK, g_w_l + (size_t)z * DIMK * DIMK,
              Lh, Ll, g_b16_h + (size_t)z * DIMK * 16, g_b16_l + (size_t)z * DIMK * 16,
              (float*)0, Ch, Cl);
}

// o projection
__global__ __launch_bounds__(256, 1)
void gemm_o_kernel(float* __restrict__ out)
{
    extern __shared__ char smem[];
    gemm_body(smem, g_att_h, g_att_l,
              g_w_h + (size_t)3 * DIMK * DIMK, g_w_l + (size_t)3 * DIMK * DIMK,
              g_lo_h, g_lo_l, g_b16_h + (size_t)3 * DIMK * 16, g_b16_l + (size_t)3 * DIMK * 16,
              out, (__nv_bfloat16*)0, (__nv_bfloat16*)0);
}

// ---------------- HMMA split-bf16 flash attention, block-causal (frame=256) ----------------
// 256 threads (8 warps), q-tile 128 rows (warp w owns rows w*16..w*16+15), key tile 64.
// Smem: Qh 0 (16KB), Ql 16384; K/V stage s at 32768+s*32768: Kh+0, Kl+8192, Vh+16384, Vl+24576.
__global__ __launch_bounds__(256, 1)
void attn_mma_kernel(float* __restrict__ o)
{
    extern __shared__ char smem[];
    const uint32_t sb = smem_u32(smem);
    int qt = 15 - (int)blockIdx.x;           // big frames first
    int h  = blockIdx.y;
    int b  = blockIdx.z;
    int t0 = qt << 7;
    int ntile = ((qt >> 1) + 1) << 2;        // key tiles of 64
    int tid = threadIdx.x, lane = tid & 31, w = tid >> 5;
    size_t base = ((size_t)b * 2048) * DIMK + h * DHEAD;

    // Q load (hi+lo): 128 rows x 128B each, 2 threads/row
    {
        int lrow = tid >> 1;
        int lsegb = (tid & 1) * 4;
        size_t g = base + (size_t)(t0 + lrow) * DIMK;
        #pragma unroll
        for (int j = 0; j < 4; ++j) {
            int seg = lsegb + j;
            uint32_t so = sb + swz128u((uint32_t)lrow * 128 + seg * 16);
            cpa16(so,         g_q_h + g + seg * 8);
            cpa16(so + 16384, g_q_l + g + seg * 8);
        }
    }
    // K/V load: 64 rows x 128B x 4 arrays, 4 threads/row
    auto load_kv = [&](int kt, int st) {
        uint32_t sv = sb + 32768 + (uint32_t)st * 32768;
        int lrow = tid >> 2;
        int lsegb = (tid & 3) * 2;
        size_t g = base + (size_t)((kt << 6) + lrow) * DIMK;
        #pragma unroll
        for (int j = 0; j < 2; ++j) {
            int seg = lsegb + j;
            uint32_t so = sv + swz128u((uint32_t)lrow * 128 + seg * 16);
            cpa16(so,         g_k_h + g + seg * 8);
            cpa16(so + 8192,  g_k_l + g + seg * 8);
            cpa16(so + 16384, g_v_h + g + seg * 8);
            cpa16(so + 24576, g_v_l + g + seg * 8);
        }
    };

    // fragment addressing
    const int rA = w * 16 + (lane & 15);
    const uint32_t qRow = (uint32_t)rA * 128;
    const uint32_t qXor = (uint32_t)((rA & 7) << 4);
    const uint32_t aK = (uint32_t)((lane >> 4) << 4);
    uint32_t kRow[4], kXor[4];
    #pragma unroll
    for (int np = 0; np < 4; ++np) {
        int rB = np * 16 + ((lane >> 4) & 1) * 8 + (lane & 7);
        kRow[np] = (uint32_t)rB * 128;
        kXor[np] = (uint32_t)((rB & 7) << 4);
    }
    const uint32_t bK = (uint32_t)(((lane >> 3) & 1) * 16);
    const int keyB = ((lane >> 3) & 1) * 8 + (lane & 7);
    const int dhB  = ((lane >> 4) & 1) * 8;
    const uint32_t vXor = (uint32_t)((lane & 7) << 4);

    float accO[8][4];
    #pragma unroll
    for (int nt = 0; nt < 8; ++nt)
        #pragma unroll
        for (int i = 0; i < 4; ++i) accO[nt][i] = 0.f;
    float mreg[2] = {-1e30f, -1e30f};
    float lreg[2] = {0.f, 0.f};

    load_kv(0, 0); CP_COMMIT();

    #pragma unroll 1
    for (int kt = 0; kt < ntile; ++kt) {
        if (kt + 1 < ntile) { load_kv(kt + 1, (kt + 1) & 1); CP_COMMIT(); CP_WAIT1(); }
        else                { CP_WAIT0(); }
        __syncthreads();
        uint32_t kb = sb + 32768 + (uint32_t)(kt & 1) * 32768;
        uint32_t vb = kb + 16384;

        // S = QK^T (3-term split)
        float s[8][4];
        #pragma unroll
        for (int nt = 0; nt < 8; ++nt)
            #pragma unroll
            for (int i = 0; i < 4; ++i) s[nt][i] = 0.f;
        #pragma unroll
        for (int ks = 0; ks < 4; ++ks) {
            uint32_t kbyte = (uint32_t)ks * 32;
            uint32_t ah[4], al[4], bh[4][4], bl[4][4];
            uint32_t ad = sb + ((qRow + kbyte + aK) ^ qXor);
            ldsm4(ah, ad);
            ldsm4(al, ad + 16384);
            #pragma unroll
            for (int np = 0; np < 4; ++np) {
                uint32_t bd = kb + ((kRow[np] + kbyte + bK) ^ kXor[np]);
                ldsm4(bh[np], bd);
                ldsm4(bl[np], bd + 8192);
            }
            #pragma unroll
            for (int np = 0; np < 4; ++np)
                #pragma unroll
                for (int hf = 0; hf < 2; ++hf) {
                    float* cc = s[np * 2 + hf];
                    mma16816(cc, ah, &bh[np][hf * 2]);
                    mma16816(cc, ah, &bl[np][hf * 2]);
                    mma16816(cc, al, &bh[np][hf * 2]);
                }
        }

        // online softmax
        #pragma unroll
        for (int i = 0; i < 2; ++i) {
            float mx = -1e30f;
            #pragma unroll
            for (int nt = 0; nt < 8; ++nt) {
                s[nt][2*i]   *= 0.125f;
                s[nt][2*i+1] *= 0.125f;
                mx = fmaxf(mx, fmaxf(s[nt][2*i], s[nt][2*i+1]));
            }
            mx = fmaxf(mx, __shfl_xor_sync(0xffffffffu, mx, 1));
            mx = fmaxf(mx, __shfl_xor_sync(0xffffffffu, mx, 2));
            float mnew = fmaxf(mreg[i], mx);
            float corr = __expf(mreg[i] - mnew);
            mreg[i] = mnew;
            float rs = 0.f;
            #pragma unroll
            for (int nt = 0; nt < 8; ++nt) {
                float p0 = __expf(s[nt][2*i]   - mnew);
                float p1 = __expf(s[nt][2*i+1] - mnew);
                s[nt][2*i] = p0; s[nt][2*i+1] = p1;
                rs += p0 + p1;
            }
            rs += __shfl_xor_sync(0xffffffffu, rs, 1);
            rs += __shfl_xor_sync(0xffffffffu, rs, 2);
            lreg[i] = lreg[i] * corr + rs;
            #pragma unroll
            for (int nt = 0; nt < 8; ++nt) {
                accO[nt][2*i]   *= corr;
                accO[nt][2*i+1] *= corr;
            }
        }

        // O += P V (3-term split); pack P per kp to limit liveness
        #pragma unroll
        for (int kp = 0; kp < 4; ++kp) {
            uint32_t paH[4], paL[4];
            #pragma unroll
            for (int q4 = 0; q4 < 4; ++q4) {
                int nt = kp * 2 + (q4 >> 1);
                int e0 = (q4 & 1) * 2;
                split2(s[nt][e0], s[nt][e0 + 1], paH[q4], paL[q4]);
            }
            uint32_t vrow = (uint32_t)(kp * 16 + keyB) * 128;
            uint32_t vbh[4][4], vbl[4][4];
            #pragma unroll
            for (int np = 0; np < 4; ++np) {
                uint32_t bd = vb + ((vrow + (uint32_t)(np * 16 + dhB) * 2) ^ vXor);
                ldsm4t(vbh[np], bd);
                ldsm4t(vbl[np], bd + 8192);
            }
            #pragma unroll
            for (int np = 0; np < 4; ++np)
                #pragma unroll
                for (int hf = 0; hf < 2; ++hf) {
                    float* cc = accO[np * 2 + hf];
                    mma16816(cc, paH, &vbh[np][hf * 2]);
                    mma16816(cc, paH, &vbl[np][hf * 2]);
                    mma16816(cc, paL, &vbh[np][hf * 2]);
                }
        }
        __syncthreads();
    }

    // epilogue: fp32 att (for o low-rank proj) + hi/lo bf16 att
    #pragma unroll
    for (int i = 0; i < 2; ++i) {
        float inv = 1.0f / lreg[i];
        int row = t0 + w * 16 + (lane >> 2) + i * 8;
        size_t rb = base + (size_t)row * DIMK;
        #pragma unroll
        for (int nt = 0; nt < 8; ++nt) {
            int col = nt * 8 + (lane & 3) * 2;
            float f0 = accO[nt][2*i] * inv, f1 = accO[nt][2*i+1] * inv;
            *(float2*)(o + rb + col) = make_float2(f0, f1);
            uint32_t hp, lp;
            split2(f0, f1, hp, lp);
            *(uint32_t*)(g_att_h + rb + col) = hp;
            *(uint32_t*)(g_att_l + rb + col) = lp;
        }
    }
}

// ---------------- launch ----------------
extern "C" void kernel_launch(void* const* d_in, const int* in_sizes, int n_in,
                              void* d_out, int out_size)
{
    (void)in_sizes; (void)n_in; (void)out_size;
    const float* x      = (const float*)d_in[0];
    const float* m_tok  = (const float*)d_in[1];
    const float* norm_g = (const float*)d_in[2];
    const float* norm_b = (const float*)d_in[3];
    const float* mnorm_g= (const float*)d_in[4];
    const float* mnorm_b= (const float*)d_in[5];
    const float* Wq = (const float*)d_in[6];
    const float* Aq = (const float*)d_in[7];
    const float* Bq = (const float*)d_in[8];
    const float* Gq = (const float*)d_in[9];
    const float* Wk = (const float*)d_in[10];
    const float* Ak = (const float*)d_in[11];
    const float* Bk = (const float*)d_in[12];
    const float* Gk = (const float*)d_in[13];
    const float* Wv = (const float*)d_in[14];
    const float* Av = (const float*)d_in[15];
    const float* Bv = (const float*)d_in[16];
    const float* Gv = (const float*)d_in[17];
    const float* Wo = (const float*)d_in[18];
    const float* Ao = (const float*)d_in[19];
    const float* Bo = (const float*)d_in[20];
    const float* Go = (const float*)d_in[21];
    float* out = (float*)d_out;

    float *p_xn, *p_mn, *p_att;
    cudaGetSymbolAddress((void**)&p_xn,  g_xn);
    cudaGetSymbolAddress((void**)&p_mn,  g_mn);
    cudaGetSymbolAddress((void**)&p_att, g_att);
    __nv_bfloat16 *p_xnh, *p_xnl;
    cudaGetSymbolAddress((void**)&p_xnh, g_xn_h);
    cudaGetSymbolAddress((void**)&p_xnl, g_xn_l);

    const int GSMEM = 2 * 65536 + 4 * 6144;        // 152 KB
    const int LSMEM = 32 * 1024 * 4 + 16 * 64 * 4; // 135 KB
    const int ASMEM = 32768 + 2 * 32768;           // 96 KB
    cudaFuncSetAttribute(gemm_qkv_kernel, cudaFuncAttributeMaxDynamicSharedMemorySize, GSMEM);
    cudaFuncSetAttribute(gemm_o_kernel,   cudaFuncAttributeMaxDynamicSharedMemorySize, GSMEM);
    cudaFuncSetAttribute(lowrank_qkv_kernel, cudaFuncAttributeMaxDynamicSharedMemorySize, LSMEM);
    cudaFuncSetAttribute(attn_mma_kernel, cudaFuncAttributeMaxDynamicSharedMemorySize, ASMEM);

    cvt_w4_kernel<<<dim3(1024, 4), 256>>>(Wq, Wk, Wv, Wo);
    cvt_b4_kernel<<<dim3(4, 4), 256>>>(Bq, Bk, Bv, Bo);

    ln_kernel<<<NTOK, 256>>>(x,     norm_g,  norm_b,  p_xn, p_xnh, p_xnl);
    ln_kernel<<<NTOK, 256>>>(m_tok, mnorm_g, mnorm_b, p_mn, ((__nv_bfloat16*)0), ((__nv_bfloat16*)0));
    lowrank_qkv_kernel<<<NTOK / 16, 256, LSMEM>>>(Aq, Ak, Av, Gq, Gk, Gv, Go);

    gemm_qkv_kernel<<<dim3(8, 32, 3), 256, GSMEM>>>();

    attn_mma_kernel<<<dim3(16, 16, 2), 256, ASMEM>>>(p_att);

    lowrank_o_kernel<<<NTOK, 128>>>(Ao);
    gemm_o_kernel<<<dim3(8, 32), 256, GSMEM>>>(out);
}